// round 4
// baseline (speedup 1.0000x reference)
#include <cuda_runtime.h>
#include <math.h>

#define B_N 1024
#define F_N 257
#define BF_N (B_N * F_N)
#define T_CORE 65
#define NBX 4
#define NPART (NBX * B_N)   // 4096
#define NT 72               // ht/kv slots per block (f = fb-1 .. fb+70)

typedef unsigned long long u64;

// -------- device scratch (allocation-free) --------
__device__ __align__(16) float g_h[2][(size_t)BF_N * 32];
__device__ __align__(16) float g_c[(size_t)BF_N * 32];
__device__ __align__(16) float g_part[64][NPART];   // [kind*32+ch][block]
__device__ __align__(16) float g_bn[2][32];

__device__ __forceinline__ float gelu_f(float x) {
    return 0.5f * x * (1.0f + erff(x * 0.70710678118654752440f));
}
__device__ __forceinline__ void ffma2(u64& d, u64 a, u64 b) {
    asm("fma.rn.f32x2 %0, %1, %2, %0;" : "+l"(d) : "l"(a), "l"(b));
}
__device__ __forceinline__ u64 pack2(float x) {
    u64 r; asm("mov.b64 %0, {%1, %1};" : "=l"(r) : "f"(x)); return r;
}
__device__ __forceinline__ float2 unpack2(u64 a) {
    float2 f; asm("mov.b64 {%0, %1}, %2;" : "=f"(f.x), "=f"(f.y) : "l"(a)); return f;
}

// ===== conv (width-3 over F) on smem y [.][36] + BN partials; all 256 threads call =====
__device__ __forceinline__ void conv_phase(const float* y, const float* cws,
                                           int fb, int E, size_t rowbase,
                                           int pidx, float* red) {
    int tid = threadIdx.x;
    int tq = tid >> 2, o0 = (tid & 3) << 3;
    float s1[8], s2[8];
#pragma unroll
    for (int j = 0; j < 8; j++) { s1[j] = 0.f; s2[j] = 0.f; }
#pragma unroll
    for (int it = 0; it < 2; it++) {
        int t = it * 64 + tq;
        if (t < E) {
            int f = fb + t;
            int s = t + 1;  // y slot for global token f
            u64 acc2[4] = {0ull, 0ull, 0ull, 0ull};
#pragma unroll
            for (int w = 0; w < 3; w++) {
                if (w == 0 && f == 0) continue;
                if (w == 2 && f == F_N - 1) continue;
                const float* yr = y + (s - 1 + w) * 36;
                const float* wb = cws + w * 1024 + o0;
#pragma unroll
                for (int i = 0; i < 32; i++) {
                    u64 a2 = pack2(yr[i]);
                    const u64* wr = (const u64*)(wb + i * 32);
                    ffma2(acc2[0], a2, wr[0]);
                    ffma2(acc2[1], a2, wr[1]);
                    ffma2(acc2[2], a2, wr[2]);
                    ffma2(acc2[3], a2, wr[3]);
                }
            }
            ulonglong2* co = (ulonglong2*)&g_c[(rowbase + f) * 32 + o0];
            co[0] = make_ulonglong2(acc2[0], acc2[1]);
            co[1] = make_ulonglong2(acc2[2], acc2[3]);
#pragma unroll
            for (int k = 0; k < 4; k++) {
                float2 f2 = unpack2(acc2[k]);
                s1[2 * k] += f2.x;     s2[2 * k] += f2.x * f2.x;
                s1[2 * k + 1] += f2.y; s2[2 * k + 1] += f2.y * f2.y;
            }
        }
    }
#pragma unroll
    for (int off = 4; off < 32; off <<= 1) {
#pragma unroll
        for (int j = 0; j < 8; j++) {
            s1[j] += __shfl_xor_sync(0xffffffffu, s1[j], off);
            s2[j] += __shfl_xor_sync(0xffffffffu, s2[j], off);
        }
    }
    int warp = tid >> 5, lane = tid & 31;
    if (lane < 4) {
#pragma unroll
        for (int j = 0; j < 8; j++) {
            red[((warp * 4 + lane) * 8 + j) * 2 + 0] = s1[j];
            red[((warp * 4 + lane) * 8 + j) * 2 + 1] = s2[j];
        }
    }
    __syncthreads();
    if (tid < 64) {
        int kind = tid >> 5, ch = tid & 31;
        int sl = ch >> 3, j = ch & 7;
        float v = 0.f;
#pragma unroll
        for (int w2 = 0; w2 < 8; w2++) v += red[((w2 * 4 + sl) * 8 + j) * 2 + kind];
        g_part[kind * 32 + ch][pidx] = v;
    }
}

// ===== k_pre: inproj (18->32) + conv layer-0 + partials =====
__global__ __launch_bounds__(256) void k_pre(const float* __restrict__ x,
                                             const float* __restrict__ in_w,
                                             const float* __restrict__ in_b,
                                             const float* __restrict__ cw0) {
    __shared__ __align__(16) float xs[68 * 19];    // also conv red area
    __shared__ __align__(16) float yb[68 * 36];
    __shared__ __align__(16) float wsin[576];
    __shared__ __align__(16) float bsin[32];
    __shared__ __align__(16) float cw[3072];
    int tid = threadIdx.x;
    int fb = blockIdx.x * T_CORE;
    int E = min(T_CORE, F_N - fb);
    size_t rowbase = (size_t)blockIdx.y * F_N;

    for (int idx = tid; idx < (E + 2) * 18; idx += 256) {
        int s = idx / 18, i = idx - s * 18;
        int f = fb - 1 + s;
        xs[s * 19 + i] = (f >= 0 && f < F_N) ? x[(rowbase + f) * 18 + i] : 0.f;
    }
    for (int idx = tid; idx < 576; idx += 256) wsin[idx] = in_w[idx];
    if (tid < 32) bsin[tid] = in_b[tid];
    for (int idx = tid; idx < 3072; idx += 256) cw[idx] = cw0[idx];
    __syncthreads();

    int s = tid;
    if (s < E + 2) {
        int f = fb - 1 + s;
        u64 acc[16];
        if (f >= 0 && f < F_N) {
            const u64* b2 = (const u64*)bsin;
#pragma unroll
            for (int k = 0; k < 16; k++) acc[k] = b2[k];
#pragma unroll
            for (int i = 0; i < 18; i++) {
                u64 a2 = pack2(xs[s * 19 + i]);
                const u64* wr = (const u64*)(wsin + i * 32);
#pragma unroll
                for (int k = 0; k < 16; k++) ffma2(acc[k], a2, wr[k]);
            }
        } else {
#pragma unroll
            for (int k = 0; k < 16; k++) acc[k] = 0ull;
        }
        ulonglong2* o = (ulonglong2*)&yb[s * 36];
#pragma unroll
        for (int k = 0; k < 8; k++) o[k] = make_ulonglong2(acc[2 * k], acc[2 * k + 1]);
    }
    __syncthreads();

    for (int idx = tid; idx < E * 32; idx += 256) {
        int t = idx >> 5, c = idx & 31;
        g_h[0][(rowbase + fb + t) * 32 + c] = yb[(t + 1) * 36 + c];
    }
    conv_phase(yb, cw, fb, E, rowbase, (int)blockIdx.y * NBX + blockIdx.x, xs);
}

// ===== BN finalize: one block per channel, coalesced over g_part rows =====
__global__ __launch_bounds__(256) void k_bnfin(const float* __restrict__ bng,
                                               const float* __restrict__ bnb) {
    __shared__ float rs[256], rq[256];
    int c = blockIdx.x;
    float s = 0.f, q = 0.f;
    for (int i = threadIdx.x; i < NPART; i += 256) {
        s += g_part[c][i];
        q += g_part[32 + c][i];
    }
    rs[threadIdx.x] = s; rq[threadIdx.x] = q;
    __syncthreads();
    for (int off = 128; off > 0; off >>= 1) {
        if (threadIdx.x < off) {
            rs[threadIdx.x] += rs[threadIdx.x + off];
            rq[threadIdx.x] += rq[threadIdx.x + off];
        }
        __syncthreads();
    }
    if (threadIdx.x == 0) {
        float mean = rs[0] * (1.0f / BF_N);
        float var = rq[0] * (1.0f / BF_N) - mean * mean;
        float a = rsqrtf(var + 1e-5f) * bng[c];
        g_bn[0][c] = a;
        g_bn[1][c] = bnb[c] - mean * a;
    }
}

// ===== fused layer: kv GEMM + banded attn (q on-the-fly) + proj + BN/GELU + LN + next-conv / head =====
// smem floats:
//   R_A [0,2448):      ht [32][72] (2304) -> y [68][36] (2448)
//   R_B [2448,7344):   kv [72][68] (4896) -> cw (3072) or head params (545)
//   R_C [7344,9588):   as_ [68][33] (2244) -> conv red (512)
//   wq  [9588,12660)   32x96
//   wp  [12660,13684)  32x32
//   params [13684,13844)
#define SMEM_APPLY (13844 * 4)
__global__ __launch_bounds__(256, 4) void k_apply(const float* __restrict__ qw,
                                                  const float* __restrict__ pw,
                                                  const float* __restrict__ pbias,
                                                  const float* __restrict__ lng,
                                                  const float* __restrict__ lnb,
                                                  const float* __restrict__ cwn,
                                                  const float* __restrict__ h1_w,
                                                  const float* __restrict__ h1_b,
                                                  const float* __restrict__ h2_w,
                                                  const float* __restrict__ h2_b,
                                                  float* __restrict__ out,
                                                  int src, int last) {
    extern __shared__ float sm[];
    float* R_A = sm;
    float* R_B = sm + 2448;
    float* R_C = sm + 7344;
    float* wq  = sm + 9588;
    float* wp  = sm + 12660;
    float* pb  = sm + 13684;
    float* lg  = pb + 32;
    float* lb  = lg + 32;
    float* bna = lb + 32;
    float* bnb = bna + 32;

    float* ht = R_A;      // [32][72] channel-major
    float* y  = R_A;      // [68][36] token-major (after Phase C)
    float* kv = R_B;      // [72][68]: k at +0, v at +32
    float* as_ = R_C;     // [68][33]

    int tid = threadIdx.x;
    int fb = blockIdx.x * T_CORE;
    int E = min(T_CORE, F_N - fb);
    size_t rowbase = (size_t)blockIdx.y * F_N;
    const float* hsrc = g_h[src];
    float* hdst = g_h[src ^ 1];

    // ---- stage h (channel-major) + weights ----
    for (int idx = tid; idx < 32 * NT; idx += 256) {
        int t = idx / NT, c2 = 0;  // avoid div: NT=72 not pow2; do proper mapping
        // remap: idx = c*NT + t
        int c = idx / NT; int tt = idx - c * NT;
        (void)t; (void)c2;
        int f = fb - 1 + tt;
        float v = (f >= 0 && f < F_N) ? hsrc[(rowbase + f) * 32 + c] : 0.f;
        ht[c * NT + tt] = v;
    }
    for (int idx = tid; idx < 3072; idx += 256) wq[idx] = qw[idx];
    for (int idx = tid; idx < 1024; idx += 256) wp[idx] = pw[idx];
    if (tid < 32) {
        pb[tid] = pbias[tid]; lg[tid] = lng[tid]; lb[tid] = lnb[tid];
        bna[tid] = g_bn[0][tid]; bnb[tid] = g_bn[1][tid];
    }
    __syncthreads();

    // ---- Phase B: kv GEMM (72 tokens x 64 ch, K=32), 2 tok x 8 ch, FFMA2 ----
    for (int sl = tid; sl < 288; sl += 256) {
        int og = sl / 36, tg = sl - og * 36;
        int t0 = tg * 2, oc = og * 8;
        u64 acc2[2][4];
#pragma unroll
        for (int a = 0; a < 2; a++)
#pragma unroll
            for (int k = 0; k < 4; k++) acc2[a][k] = 0ull;
#pragma unroll
        for (int i = 0; i < 32; i++) {
            float2 av = *reinterpret_cast<const float2*>(&ht[i * NT + t0]);
            const u64* wr = reinterpret_cast<const u64*>(&wq[i * 96 + 32 + oc]);
            u64 w0 = wr[0], w1 = wr[1], w2 = wr[2], w3 = wr[3];
            u64 a0 = pack2(av.x), a1 = pack2(av.y);
            ffma2(acc2[0][0], a0, w0); ffma2(acc2[0][1], a0, w1); ffma2(acc2[0][2], a0, w2); ffma2(acc2[0][3], a0, w3);
            ffma2(acc2[1][0], a1, w0); ffma2(acc2[1][1], a1, w1); ffma2(acc2[1][2], a1, w2); ffma2(acc2[1][3], a1, w3);
        }
#pragma unroll
        for (int a = 0; a < 2; a++) {
            ulonglong2* dst = reinterpret_cast<ulonglong2*>(&kv[(t0 + a) * 68 + oc]);
            dst[0] = make_ulonglong2(acc2[a][0], acc2[a][1]);
            dst[1] = make_ulonglong2(acc2[a][2], acc2[a][3]);
        }
    }
    __syncthreads();

    // ---- Phase C: q on-the-fly + banded softmax + V-mix -> as_ ----
    int warp = tid >> 5, lane = tid & 31;
    for (int rep = 0; rep < 9; rep++) {
        int s = rep * 8 + warp;
        if (s >= E + 2) break;
        int f = fb - 1 + s;
        if (f >= 0 && f < F_N) {
            float q = 0.f;
#pragma unroll
            for (int i = 0; i < 32; i++) q += ht[i * NT + s] * wq[i * 96 + lane];
            float sc[3];
#pragma unroll
            for (int j = 0; j < 3; j++) {
                float p = q * kv[(s + j) * 68 + lane];
                p += __shfl_xor_sync(0xffffffffu, p, 1);
                p += __shfl_xor_sync(0xffffffffu, p, 2);
                p += __shfl_xor_sync(0xffffffffu, p, 4);
                sc[j] = (f + j < F_N) ? p * 0.35355339059327373f : -INFINITY;
            }
            float m = fmaxf(sc[0], fmaxf(sc[1], sc[2]));
            float e0 = __expf(sc[0] - m);
            float e1 = (f + 1 < F_N) ? __expf(sc[1] - m) : 0.f;
            float e2 = (f + 2 < F_N) ? __expf(sc[2] - m) : 0.f;
            float inv = 1.f / (e0 + e1 + e2);
            float ao = (e0 * kv[s * 68 + 32 + lane]
                      + e1 * kv[(s + 1) * 68 + 32 + lane]
                      + e2 * kv[(s + 2) * 68 + 32 + lane]) * inv;
            as_[s * 33 + lane] = ao;
        } else {
            as_[s * 33 + lane] = 0.f;
        }
    }
    __syncthreads();

    // kv dead: overlay conv weights (or head params) into R_B
    if (!last) {
        for (int idx = tid; idx < 3072; idx += 256) R_B[idx] = cwn[idx];
    } else {
        for (int idx = tid; idx < 512; idx += 256) R_B[idx] = h1_w[idx];
        if (tid < 16) { R_B[512 + tid] = h1_b[tid]; R_B[528 + tid] = h2_w[tid]; }
        if (tid == 0) R_B[544] = h2_b[0];
    }

    // ---- Phase D: proj + BN(c)/GELU + residual -> y (overwrites ht) ----
    for (int sl = tid; sl < (E + 2) * 4; sl += 256) {
        int s = sl >> 2, o0 = (sl & 3) << 3;
        int f = fb - 1 + s;
        if (f >= 0 && f < F_N) {
            u64 acc2[4];
            const u64* pb2 = (const u64*)(pb + o0);
            acc2[0] = pb2[0]; acc2[1] = pb2[1]; acc2[2] = pb2[2]; acc2[3] = pb2[3];
#pragma unroll
            for (int i = 0; i < 32; i++) {
                u64 a2 = pack2(as_[s * 33 + i]);
                const u64* wr = (const u64*)(wp + i * 32 + o0);
                ffma2(acc2[0], a2, wr[0]);
                ffma2(acc2[1], a2, wr[1]);
                ffma2(acc2[2], a2, wr[2]);
                ffma2(acc2[3], a2, wr[3]);
            }
            const float4* cg = (const float4*)&g_c[(rowbase + f) * 32 + o0];
            float4 c0 = cg[0], c1 = cg[1];
            float cv[8] = {c0.x, c0.y, c0.z, c0.w, c1.x, c1.y, c1.z, c1.w};
            float yv[8];
#pragma unroll
            for (int k = 0; k < 4; k++) {
                float2 pa = unpack2(acc2[k]);
                float cn0 = cv[2 * k] * bna[o0 + 2 * k] + bnb[o0 + 2 * k];
                float cn1 = cv[2 * k + 1] * bna[o0 + 2 * k + 1] + bnb[o0 + 2 * k + 1];
                yv[2 * k] = gelu_f(cn0) + pa.x;
                yv[2 * k + 1] = gelu_f(cn1) + pa.y;
            }
            float4* yo = (float4*)&y[s * 36 + o0];
            yo[0] = make_float4(yv[0], yv[1], yv[2], yv[3]);
            yo[1] = make_float4(yv[4], yv[5], yv[6], yv[7]);
        } else {
            float4* yo = (float4*)&y[s * 36 + o0];
            yo[0] = make_float4(0.f, 0.f, 0.f, 0.f);
            yo[1] = make_float4(0.f, 0.f, 0.f, 0.f);
        }
    }
    __syncthreads();

    // ---- Phase E: LayerNorm (in place); last layer also computes head ----
    for (int rep = 0; rep < 9; rep++) {
        int s = rep * 8 + warp;
        if (s >= E + 2) break;
        int f = fb - 1 + s;
        if (f >= 0 && f < F_N) {
            float yv = y[s * 36 + lane];
            float su = yv;
#pragma unroll
            for (int off = 1; off < 32; off <<= 1) su += __shfl_xor_sync(0xffffffffu, su, off);
            float mean = su * (1.f / 32.f);
            float d = yv - mean;
            float v = d * d;
#pragma unroll
            for (int off = 1; off < 32; off <<= 1) v += __shfl_xor_sync(0xffffffffu, v, off);
            float o = d * rsqrtf(v * (1.f / 32.f) + 1e-5f) * lg[lane] + lb[lane];
            if (!last) {
                y[s * 36 + lane] = o;
            } else if (s >= 1 && s <= E) {
                // head: gelu(o@W1+b1) @ W2 + b2 -> sigmoid
                float m = R_B[544];
#pragma unroll
                for (int j = 0; j < 16; j++) {
                    float t = o * R_B[lane * 16 + j];
                    t += __shfl_xor_sync(0xffffffffu, t, 16);
                    t += __shfl_xor_sync(0xffffffffu, t, 8);
                    t += __shfl_xor_sync(0xffffffffu, t, 4);
                    t += __shfl_xor_sync(0xffffffffu, t, 2);
                    t += __shfl_xor_sync(0xffffffffu, t, 1);
                    m += gelu_f(t + R_B[512 + j]) * R_B[528 + j];
                }
                if (lane == 0) out[rowbase + f] = 1.f / (1.f + expf(-m));
            }
        }
    }
    if (last) return;
    __syncthreads();

    // ---- write h_{l+1} (core) + next-layer conv on smem y ----
    for (int idx = tid; idx < E * 32; idx += 256) {
        int t = idx >> 5, c = idx & 31;
        hdst[(rowbase + fb + t) * 32 + c] = y[(t + 1) * 36 + c];
    }
    conv_phase(y, R_B, fb, E, rowbase, (int)blockIdx.y * NBX + blockIdx.x, R_C);
}

// ===== launcher =====
extern "C" void kernel_launch(void* const* d_in, const int* in_sizes, int n_in,
                              void* d_out, int out_size) {
    const float* x      = (const float*)d_in[0];
    const float* in_w   = (const float*)d_in[1];
    const float* in_b   = (const float*)d_in[2];
    const float* conv_w = (const float*)d_in[3];
    const float* bn_g   = (const float*)d_in[4];
    const float* bn_b   = (const float*)d_in[5];
    const float* qkv_w  = (const float*)d_in[6];
    const float* proj_w = (const float*)d_in[7];
    const float* proj_b = (const float*)d_in[8];
    const float* ln_g   = (const float*)d_in[9];
    const float* ln_b   = (const float*)d_in[10];
    const float* h1_w   = (const float*)d_in[11];
    const float* h1_b   = (const float*)d_in[12];
    const float* h2_w   = (const float*)d_in[13];
    const float* h2_b   = (const float*)d_in[14];
    float* out = (float*)d_out;

    cudaFuncSetAttribute(k_apply, cudaFuncAttributeMaxDynamicSharedMemorySize, SMEM_APPLY);

    dim3 grid(NBX, B_N);
    k_pre<<<grid, 256>>>(x, in_w, in_b, conv_w);
    for (int l = 0; l < 4; l++) {
        int src = l & 1;
        int last = (l == 3) ? 1 : 0;
        k_bnfin<<<32, 256>>>(bn_g + l * 32, bn_b + l * 32);
        k_apply<<<grid, 256, SMEM_APPLY>>>(qkv_w + l * 3072, proj_w + l * 1024,
                                           proj_b + l * 32, ln_g + l * 32, ln_b + l * 32,
                                           conv_w + (l + 1 < 4 ? l + 1 : 0) * 3072,
                                           h1_w, h1_b, h2_w, h2_b, out, src, last);
    }
}

// round 7
// speedup vs baseline: 2.0194x; 2.0194x over previous
#include <cuda_runtime.h>
#include <math.h>

#define B_N 1024
#define F_N 257
#define BF_N (B_N * F_N)
#define T_CORE 65
#define NBX 4
#define NPART (NBX * B_N)   // 4096

typedef unsigned long long u64;

// -------- device scratch (allocation-free) --------
__device__ __align__(16) float g_h[2][(size_t)BF_N * 32];
__device__ __align__(16) float g_c[2][(size_t)BF_N * 32];   // ping-pong per layer (race fix)
__device__ __align__(16) float g_part[64][NPART];           // [kind*32+ch][block]
__device__ __align__(16) float g_bn[2][32];

__device__ __forceinline__ float gelu_f(float x) {
    return 0.5f * x * (1.0f + erff(x * 0.70710678118654752440f));
}
__device__ __forceinline__ void ffma2(u64& d, u64 a, u64 b) {
    asm("fma.rn.f32x2 %0, %1, %2, %0;" : "+l"(d) : "l"(a), "l"(b));
}
__device__ __forceinline__ u64 pack2(float x) {
    u64 r; asm("mov.b64 %0, {%1, %1};" : "=l"(r) : "f"(x)); return r;
}
__device__ __forceinline__ float2 unpack2(u64 a) {
    float2 f; asm("mov.b64 {%0, %1}, %2;" : "=f"(f.x), "=f"(f.y) : "l"(a)); return f;
}

// ===== conv (width-3 over F) on smem y [.][36] + BN partials; ALL 256 threads call =====
__device__ __forceinline__ void conv_phase(const float* y, const float* cws,
                                           int fb, int E, size_t rowbase,
                                           int pidx, float* red, float* gc_out) {
    int tid = threadIdx.x;
    int tq = tid >> 2, o0 = (tid & 3) << 3;
    float s1[8], s2[8];
#pragma unroll
    for (int j = 0; j < 8; j++) { s1[j] = 0.f; s2[j] = 0.f; }
#pragma unroll
    for (int it = 0; it < 2; it++) {
        int t = it * 64 + tq;
        if (t < E) {
            int f = fb + t;
            int s = t + 1;  // y slot for global token f
            u64 acc2[4] = {0ull, 0ull, 0ull, 0ull};
#pragma unroll
            for (int w = 0; w < 3; w++) {
                if (w == 0 && f == 0) continue;
                if (w == 2 && f == F_N - 1) continue;
                const float* yr = y + (s - 1 + w) * 36;
                const float* wb = cws + w * 1024 + o0;
#pragma unroll
                for (int i = 0; i < 32; i++) {
                    u64 a2 = pack2(yr[i]);
                    const u64* wr = (const u64*)(wb + i * 32);
                    ffma2(acc2[0], a2, wr[0]);
                    ffma2(acc2[1], a2, wr[1]);
                    ffma2(acc2[2], a2, wr[2]);
                    ffma2(acc2[3], a2, wr[3]);
                }
            }
            ulonglong2* co = (ulonglong2*)&gc_out[(rowbase + f) * 32 + o0];
            co[0] = make_ulonglong2(acc2[0], acc2[1]);
            co[1] = make_ulonglong2(acc2[2], acc2[3]);
#pragma unroll
            for (int k = 0; k < 4; k++) {
                float2 f2 = unpack2(acc2[k]);
                s1[2 * k] += f2.x;     s2[2 * k] += f2.x * f2.x;
                s1[2 * k + 1] += f2.y; s2[2 * k + 1] += f2.y * f2.y;
            }
        }
    }
#pragma unroll
    for (int off = 4; off < 32; off <<= 1) {
#pragma unroll
        for (int j = 0; j < 8; j++) {
            s1[j] += __shfl_xor_sync(0xffffffffu, s1[j], off);
            s2[j] += __shfl_xor_sync(0xffffffffu, s2[j], off);
        }
    }
    int warp = tid >> 5, lane = tid & 31;
    if (lane < 4) {
#pragma unroll
        for (int j = 0; j < 8; j++) {
            red[((warp * 4 + lane) * 8 + j) * 2 + 0] = s1[j];
            red[((warp * 4 + lane) * 8 + j) * 2 + 1] = s2[j];
        }
    }
    __syncthreads();
    if (tid < 64) {
        int kind = tid >> 5, ch = tid & 31;
        int sl = ch >> 3, j = ch & 7;
        float v = 0.f;
#pragma unroll
        for (int w2 = 0; w2 < 8; w2++) v += red[((w2 * 4 + sl) * 8 + j) * 2 + kind];
        g_part[kind * 32 + ch][pidx] = v;
    }
}

// ===== k_pre: inproj (18->32) + conv layer-0 + partials =====
__global__ __launch_bounds__(256) void k_pre(const float* __restrict__ x,
                                             const float* __restrict__ in_w,
                                             const float* __restrict__ in_b,
                                             const float* __restrict__ cw0) {
    __shared__ __align__(16) float xs[68 * 19];    // also conv red area
    __shared__ __align__(16) float yb[68 * 36];
    __shared__ __align__(16) float wsin[576];
    __shared__ __align__(16) float bsin[32];
    __shared__ __align__(16) float cw[3072];
    int tid = threadIdx.x;
    int fb = blockIdx.x * T_CORE;
    int E = min(T_CORE, F_N - fb);
    size_t rowbase = (size_t)blockIdx.y * F_N;

    for (int idx = tid; idx < (E + 2) * 18; idx += 256) {
        int s = idx / 18, i = idx - s * 18;
        int f = fb - 1 + s;
        xs[s * 19 + i] = (f >= 0 && f < F_N) ? x[(rowbase + f) * 18 + i] : 0.f;
    }
    for (int idx = tid; idx < 576; idx += 256) wsin[idx] = in_w[idx];
    if (tid < 32) bsin[tid] = in_b[tid];
    for (int idx = tid; idx < 3072; idx += 256) cw[idx] = cw0[idx];
    __syncthreads();

    int s = tid;
    if (s < E + 2) {
        int f = fb - 1 + s;
        u64 acc[16];
        if (f >= 0 && f < F_N) {
            const u64* b2 = (const u64*)bsin;
#pragma unroll
            for (int k = 0; k < 16; k++) acc[k] = b2[k];
#pragma unroll
            for (int i = 0; i < 18; i++) {
                u64 a2 = pack2(xs[s * 19 + i]);
                const u64* wr = (const u64*)(wsin + i * 32);
#pragma unroll
                for (int k = 0; k < 16; k++) ffma2(acc[k], a2, wr[k]);
            }
        } else {
#pragma unroll
            for (int k = 0; k < 16; k++) acc[k] = 0ull;
        }
        ulonglong2* o = (ulonglong2*)&yb[s * 36];
#pragma unroll
        for (int k = 0; k < 8; k++) o[k] = make_ulonglong2(acc[2 * k], acc[2 * k + 1]);
    }
    __syncthreads();

    for (int idx = tid; idx < E * 32; idx += 256) {
        int t = idx >> 5, c = idx & 31;
        g_h[0][(rowbase + fb + t) * 32 + c] = yb[(t + 1) * 36 + c];
    }
    conv_phase(yb, cw, fb, E, rowbase, (int)blockIdx.y * NBX + blockIdx.x, xs, g_c[0]);
}

// ===== BN finalize: one block per channel, coalesced =====
__global__ __launch_bounds__(256) void k_bnfin(const float* __restrict__ bng,
                                               const float* __restrict__ bnb) {
    __shared__ float rs[256], rq[256];
    int c = blockIdx.x;
    float s = 0.f, q = 0.f;
    for (int i = threadIdx.x; i < NPART; i += 256) {
        s += g_part[c][i];
        q += g_part[32 + c][i];
    }
    rs[threadIdx.x] = s; rq[threadIdx.x] = q;
    __syncthreads();
    for (int off = 128; off > 0; off >>= 1) {
        if (threadIdx.x < off) {
            rs[threadIdx.x] += rs[threadIdx.x + off];
            rq[threadIdx.x] += rq[threadIdx.x + off];
        }
        __syncthreads();
    }
    if (threadIdx.x == 0) {
        float mean = rs[0] * (1.0f / BF_N);
        float var = rq[0] * (1.0f / BF_N) - mean * mean;
        float a = rsqrtf(var + 1e-5f) * bng[c];
        g_bn[0][c] = a;
        g_bn[1][c] = bnb[c] - mean * a;
    }
}

// ===== fused layer: qkv GEMM + banded attn + proj + BN/GELU + LN + next-layer conv =====
// Attention slots s = 0..66 (f = fb-1 .. fb+65): core s=1..E, halos for conv.
// smem floats:
//   R1 [0,2304):        ht [32][72] channel-major -> as_ [67][33] (2211) after Phase B
//   qs [2304,9504):     [72][100] q|k|v token-major -> y [67][36] (2412) + cw (3072 at +2412)
//   wq [9504,12576)     32x96
//   wp [12576,13600)    32x32
//   params [13600,13760)
#define SMEM_APPLY (13760 * 4)
__global__ __launch_bounds__(256) void k_apply(const float* __restrict__ qw,
                                               const float* __restrict__ pw,
                                               const float* __restrict__ pbias,
                                               const float* __restrict__ lng,
                                               const float* __restrict__ lnb,
                                               const float* __restrict__ cwn,
                                               int src, int cidx, int last) {
    extern __shared__ float sm[];
    float* R1 = sm;               // ht then as_
    float* qs = sm + 2304;        // [72][100], later y + cw
    float* wq = sm + 9504;
    float* wp = sm + 12576;
    float* pb = sm + 13600;
    float* lg = pb + 32;
    float* lb = lg + 32;
    float* bna = lb + 32;
    float* bnb = bna + 32;

    float* ht = R1;               // [32][72]
    float* as_ = R1;              // [67][33] (after B; ht dead)
    float* y = qs;                // [67][36] (after C; qs rows dead)
    float* cw = qs + 2412;        // 3072 floats

    int tid = threadIdx.x;
    int fb = blockIdx.x * T_CORE;
    int E = min(T_CORE, F_N - fb);
    size_t rowbase = (size_t)blockIdx.y * F_N;
    const float* hsrc = g_h[src];
    float* hdst = g_h[src ^ 1];
    const float* gc_in = g_c[cidx];
    float* gc_out = g_c[cidx ^ 1];

    // ---- stage ht channel-major ----
    for (int idx = tid; idx < 32 * 72; idx += 256) {
        int c = idx / 72, t = idx - c * 72;
        int f = fb - 1 + t;
        ht[c * 72 + t] = (f >= 0 && f < F_N) ? hsrc[(rowbase + f) * 32 + c] : 0.f;
    }
    for (int idx = tid; idx < 3072; idx += 256) wq[idx] = qw[idx];
    for (int idx = tid; idx < 1024; idx += 256) wp[idx] = pw[idx];
    if (tid < 32) {
        pb[tid] = pbias[tid]; lg[tid] = lng[tid]; lb[tid] = lnb[tid];
        bna[tid] = g_bn[0][tid]; bnb[tid] = g_bn[1][tid];
    }
    __syncthreads();

    // ---- Phase B: qkv GEMM (72 tok x 96 ch, K=32), 4 tok x 8 ch, FFMA2; 216 units ----
    if (tid < 216) {
        int og = tid / 18, tg = tid - og * 18;
        int t0 = tg * 4, oc = og * 8;
        u64 acc2[4][4];
#pragma unroll
        for (int a = 0; a < 4; a++)
#pragma unroll
            for (int k = 0; k < 4; k++) acc2[a][k] = 0ull;
#pragma unroll
        for (int i = 0; i < 32; i++) {
            float4 av = *reinterpret_cast<const float4*>(&ht[i * 72 + t0]);
            const u64* wr = reinterpret_cast<const u64*>(&wq[i * 96 + oc]);
            u64 w0 = wr[0], w1 = wr[1], w2 = wr[2], w3 = wr[3];
            u64 a0 = pack2(av.x), a1 = pack2(av.y), a2 = pack2(av.z), a3 = pack2(av.w);
            ffma2(acc2[0][0], a0, w0); ffma2(acc2[0][1], a0, w1); ffma2(acc2[0][2], a0, w2); ffma2(acc2[0][3], a0, w3);
            ffma2(acc2[1][0], a1, w0); ffma2(acc2[1][1], a1, w1); ffma2(acc2[1][2], a1, w2); ffma2(acc2[1][3], a1, w3);
            ffma2(acc2[2][0], a2, w0); ffma2(acc2[2][1], a2, w1); ffma2(acc2[2][2], a2, w2); ffma2(acc2[2][3], a2, w3);
            ffma2(acc2[3][0], a3, w0); ffma2(acc2[3][1], a3, w1); ffma2(acc2[3][2], a3, w2); ffma2(acc2[3][3], a3, w3);
        }
#pragma unroll
        for (int a = 0; a < 4; a++) {
            ulonglong2* dst = reinterpret_cast<ulonglong2*>(&qs[(t0 + a) * 100 + oc]);
            dst[0] = make_ulonglong2(acc2[a][0], acc2[a][1]);
            dst[1] = make_ulonglong2(acc2[a][2], acc2[a][3]);
        }
    }
    __syncthreads();

    // ---- Phase C: banded attention, warp per slot (lane=channel) -> as_ (over dead ht) ----
    int warp = tid >> 5, lane = tid & 31;
    for (int rep = 0; rep < 9; rep++) {
        int s = rep * 8 + warp;
        if (s >= 67) break;
        int f = fb - 1 + s;
        if (f >= 0 && f < F_N) {
            float qv = qs[s * 100 + lane];
            float sc[3];
#pragma unroll
            for (int j = 0; j < 3; j++) {
                float p = qv * qs[(s + j) * 100 + 32 + lane];
                p += __shfl_xor_sync(0xffffffffu, p, 1);
                p += __shfl_xor_sync(0xffffffffu, p, 2);
                p += __shfl_xor_sync(0xffffffffu, p, 4);
                sc[j] = (f + j < F_N) ? p * 0.35355339059327373f : -INFINITY;
            }
            float m = fmaxf(sc[0], fmaxf(sc[1], sc[2]));
            float e0 = __expf(sc[0] - m);
            float e1 = (f + 1 < F_N) ? __expf(sc[1] - m) : 0.f;
            float e2 = (f + 2 < F_N) ? __expf(sc[2] - m) : 0.f;
            float inv = 1.f / (e0 + e1 + e2);
            float ao = (e0 * qs[s * 100 + 64 + lane]
                      + e1 * qs[(s + 1) * 100 + 64 + lane]
                      + e2 * qs[(s + 2) * 100 + 64 + lane]) * inv;
            as_[s * 33 + lane] = ao;
        } else {
            as_[s * 33 + lane] = 0.f;
        }
    }
    __syncthreads();

    // qs rows dead: overlay next-layer conv weights (disjoint from y region)
    if (!last)
        for (int idx = tid; idx < 3072; idx += 256) cw[idx] = cwn[idx];

    // ---- Phase D: proj + BN(c)/GELU + residual -> y (over dead qs rows) ----
    for (int sl = tid; sl < 67 * 4; sl += 256) {
        int s = sl >> 2, o0 = (sl & 3) << 3;
        int f = fb - 1 + s;
        if (f >= 0 && f < F_N) {
            u64 acc2[4];
            const u64* pb2 = (const u64*)(pb + o0);
            acc2[0] = pb2[0]; acc2[1] = pb2[1]; acc2[2] = pb2[2]; acc2[3] = pb2[3];
#pragma unroll
            for (int i = 0; i < 32; i++) {
                u64 a2 = pack2(as_[s * 33 + i]);
                const u64* wr = (const u64*)(wp + i * 32 + o0);
                ffma2(acc2[0], a2, wr[0]);
                ffma2(acc2[1], a2, wr[1]);
                ffma2(acc2[2], a2, wr[2]);
                ffma2(acc2[3], a2, wr[3]);
            }
            const float4* cg = (const float4*)&gc_in[(rowbase + f) * 32 + o0];
            float4 c0 = cg[0], c1 = cg[1];
            float cv[8] = {c0.x, c0.y, c0.z, c0.w, c1.x, c1.y, c1.z, c1.w};
            float yv[8];
#pragma unroll
            for (int k = 0; k < 4; k++) {
                float2 pa = unpack2(acc2[k]);
                float cn0 = cv[2 * k] * bna[o0 + 2 * k] + bnb[o0 + 2 * k];
                float cn1 = cv[2 * k + 1] * bna[o0 + 2 * k + 1] + bnb[o0 + 2 * k + 1];
                yv[2 * k] = gelu_f(cn0) + pa.x;
                yv[2 * k + 1] = gelu_f(cn1) + pa.y;
            }
            float4* yo = (float4*)&y[s * 36 + o0];
            yo[0] = make_float4(yv[0], yv[1], yv[2], yv[3]);
            yo[1] = make_float4(yv[4], yv[5], yv[6], yv[7]);
        } else {
            float4* yo = (float4*)&y[s * 36 + o0];
            yo[0] = make_float4(0.f, 0.f, 0.f, 0.f);
            yo[1] = make_float4(0.f, 0.f, 0.f, 0.f);
        }
    }
    __syncthreads();

    // ---- Phase E: LayerNorm in place ----
    for (int rep = 0; rep < 9; rep++) {
        int s = rep * 8 + warp;
        if (s >= 67) break;
        int f = fb - 1 + s;
        if (f >= 0 && f < F_N) {
            float yv = y[s * 36 + lane];
            float su = yv;
#pragma unroll
            for (int off = 1; off < 32; off <<= 1) su += __shfl_xor_sync(0xffffffffu, su, off);
            float mean = su * (1.f / 32.f);
            float d = yv - mean;
            float v = d * d;
#pragma unroll
            for (int off = 1; off < 32; off <<= 1) v += __shfl_xor_sync(0xffffffffu, v, off);
            y[s * 36 + lane] = d * rsqrtf(v * (1.f / 32.f) + 1e-5f) * lg[lane] + lb[lane];
        }
    }
    __syncthreads();

    // ---- write h_{l+1} (core) + fused next-layer conv ----
    for (int idx = tid; idx < E * 32; idx += 256) {
        int t = idx >> 5, c = idx & 31;
        hdst[(rowbase + fb + t) * 32 + c] = y[(t + 1) * 36 + c];
    }
    if (!last)
        conv_phase(y, cw, fb, E, rowbase, (int)blockIdx.y * NBX + blockIdx.x, R1, gc_out);
}

// ===== head: gelu(h@W1+b1) @ W2 + b2 -> sigmoid =====
__global__ __launch_bounds__(256) void k_head(const float* __restrict__ w1,
                                              const float* __restrict__ b1,
                                              const float* __restrict__ w2,
                                              const float* __restrict__ b2,
                                              float* __restrict__ out) {
    __shared__ __align__(16) float hsm[256][33];
    __shared__ __align__(16) float ws1[512];
    __shared__ __align__(16) float wb1[16];
    __shared__ __align__(16) float ws2[16];
    __shared__ float b2s;
    int t0 = blockIdx.x * 256;
    const float* hsrc = g_h[0];
    for (int idx = threadIdx.x; idx < 256 * 32; idx += 256) {
        int tok = idx >> 5, c = idx & 31;
        hsm[tok][c] = hsrc[(size_t)(t0 + tok) * 32 + c];
    }
    for (int idx = threadIdx.x; idx < 512; idx += 256) ws1[idx] = w1[idx];
    if (threadIdx.x < 16) { wb1[threadIdx.x] = b1[threadIdx.x]; ws2[threadIdx.x] = w2[threadIdx.x]; }
    if (threadIdx.x == 0) b2s = b2[0];
    __syncthreads();

    const float* hr = hsm[threadIdx.x];
    u64 s2[8];
    const u64* wb2 = (const u64*)wb1;
#pragma unroll
    for (int k = 0; k < 8; k++) s2[k] = wb2[k];
#pragma unroll
    for (int i = 0; i < 32; i++) {
        u64 a2 = pack2(hr[i]);
        const u64* wr = (const u64*)(ws1 + i * 16);
#pragma unroll
        for (int k = 0; k < 8; k++) ffma2(s2[k], a2, wr[k]);
    }
    float m = b2s;
#pragma unroll
    for (int k = 0; k < 8; k++) {
        float2 f2 = unpack2(s2[k]);
        m += gelu_f(f2.x) * ws2[2 * k] + gelu_f(f2.y) * ws2[2 * k + 1];
    }
    out[t0 + threadIdx.x] = 1.f / (1.f + expf(-m));
}

// ===== launcher =====
extern "C" void kernel_launch(void* const* d_in, const int* in_sizes, int n_in,
                              void* d_out, int out_size) {
    const float* x      = (const float*)d_in[0];
    const float* in_w   = (const float*)d_in[1];
    const float* in_b   = (const float*)d_in[2];
    const float* conv_w = (const float*)d_in[3];
    const float* bn_g   = (const float*)d_in[4];
    const float* bn_b   = (const float*)d_in[5];
    const float* qkv_w  = (const float*)d_in[6];
    const float* proj_w = (const float*)d_in[7];
    const float* proj_b = (const float*)d_in[8];
    const float* ln_g   = (const float*)d_in[9];
    const float* ln_b   = (const float*)d_in[10];
    const float* h1_w   = (const float*)d_in[11];
    const float* h1_b   = (const float*)d_in[12];
    const float* h2_w   = (const float*)d_in[13];
    const float* h2_b   = (const float*)d_in[14];
    float* out = (float*)d_out;

    cudaFuncSetAttribute(k_apply, cudaFuncAttributeMaxDynamicSharedMemorySize, SMEM_APPLY);

    dim3 grid(NBX, B_N);
    k_pre<<<grid, 256>>>(x, in_w, in_b, conv_w);
    for (int l = 0; l < 4; l++) {
        int src = l & 1;
        int cidx = l & 1;   // layer l reads g_c[l&1], writes g_c[(l&1)^1]
        int last = (l == 3) ? 1 : 0;
        k_bnfin<<<32, 256>>>(bn_g + l * 32, bn_b + l * 32);
        k_apply<<<grid, 256, SMEM_APPLY>>>(qkv_w + l * 3072, proj_w + l * 1024,
                                           proj_b + l * 32, ln_g + l * 32, ln_b + l * 32,
                                           conv_w + (l + 1 < 4 ? l + 1 : 0) * 3072,
                                           src, cidx, last);
    }
    k_head<<<BF_N / 256, 256>>>(h1_w, h1_b, h2_w, h2_b, out);
}

// round 8
// speedup vs baseline: 2.1898x; 1.0844x over previous
#include <cuda_runtime.h>
#include <math.h>

#define B_N 1024
#define F_N 257
#define BF_N (B_N * F_N)
#define T_CORE 65
#define NBX 4
#define NPART (NBX * B_N)   // 4096

typedef unsigned long long u64;

// -------- device scratch (allocation-free) --------
__device__ __align__(16) float g_h[2][(size_t)BF_N * 32];
__device__ __align__(16) float g_c[2][(size_t)BF_N * 32];   // ping-pong per layer
__device__ __align__(16) float g_part[64][NPART];           // [kind*32+ch][block]
__device__ __align__(16) float g_bn[2][32];

__device__ __forceinline__ float gelu_f(float x) {
    return 0.5f * x * (1.0f + erff(x * 0.70710678118654752440f));
}
__device__ __forceinline__ void ffma2(u64& d, u64 a, u64 b) {
    asm("fma.rn.f32x2 %0, %1, %2, %0;" : "+l"(d) : "l"(a), "l"(b));
}
__device__ __forceinline__ u64 pack2(float x) {
    u64 r; asm("mov.b64 %0, {%1, %1};" : "=l"(r) : "f"(x)); return r;
}
__device__ __forceinline__ float2 unpack2(u64 a) {
    float2 f; asm("mov.b64 {%0, %1}, %2;" : "=f"(f.x), "=f"(f.y) : "l"(a)); return f;
}

// ===== conv (width-3 over F) on smem y [.][36] + BN partials; ALL 256 threads call =====
__device__ __forceinline__ void conv_phase(const float* y, const float* cws,
                                           int fb, int E, size_t rowbase,
                                           int pidx, float* red, float* gc_out) {
    int tid = threadIdx.x;
    int tq = tid >> 2, o0 = (tid & 3) << 3;
    float s1[8], s2[8];
#pragma unroll
    for (int j = 0; j < 8; j++) { s1[j] = 0.f; s2[j] = 0.f; }
#pragma unroll
    for (int it = 0; it < 2; it++) {
        int t = it * 64 + tq;
        if (t < E) {
            int f = fb + t;
            int s = t + 1;  // y slot for global token f
            u64 acc2[4] = {0ull, 0ull, 0ull, 0ull};
#pragma unroll
            for (int w = 0; w < 3; w++) {
                if (w == 0 && f == 0) continue;
                if (w == 2 && f == F_N - 1) continue;
                const float* yr = y + (s - 1 + w) * 36;
                const float* wb = cws + w * 1024 + o0;
#pragma unroll
                for (int i = 0; i < 32; i++) {
                    u64 a2 = pack2(yr[i]);
                    const u64* wr = (const u64*)(wb + i * 32);
                    ffma2(acc2[0], a2, wr[0]);
                    ffma2(acc2[1], a2, wr[1]);
                    ffma2(acc2[2], a2, wr[2]);
                    ffma2(acc2[3], a2, wr[3]);
                }
            }
            ulonglong2* co = (ulonglong2*)&gc_out[(rowbase + f) * 32 + o0];
            co[0] = make_ulonglong2(acc2[0], acc2[1]);
            co[1] = make_ulonglong2(acc2[2], acc2[3]);
#pragma unroll
            for (int k = 0; k < 4; k++) {
                float2 f2 = unpack2(acc2[k]);
                s1[2 * k] += f2.x;     s2[2 * k] += f2.x * f2.x;
                s1[2 * k + 1] += f2.y; s2[2 * k + 1] += f2.y * f2.y;
            }
        }
    }
#pragma unroll
    for (int off = 4; off < 32; off <<= 1) {
#pragma unroll
        for (int j = 0; j < 8; j++) {
            s1[j] += __shfl_xor_sync(0xffffffffu, s1[j], off);
            s2[j] += __shfl_xor_sync(0xffffffffu, s2[j], off);
        }
    }
    int warp = tid >> 5, lane = tid & 31;
    if (lane < 4) {
#pragma unroll
        for (int j = 0; j < 8; j++) {
            red[((warp * 4 + lane) * 8 + j) * 2 + 0] = s1[j];
            red[((warp * 4 + lane) * 8 + j) * 2 + 1] = s2[j];
        }
    }
    __syncthreads();
    if (tid < 64) {
        int kind = tid >> 5, ch = tid & 31;
        int sl = ch >> 3, j = ch & 7;
        float v = 0.f;
#pragma unroll
        for (int w2 = 0; w2 < 8; w2++) v += red[((w2 * 4 + sl) * 8 + j) * 2 + kind];
        g_part[kind * 32 + ch][pidx] = v;
    }
}

// ===== k_pre: inproj (18->32) + conv layer-0 + partials =====
__global__ __launch_bounds__(256) void k_pre(const float* __restrict__ x,
                                             const float* __restrict__ in_w,
                                             const float* __restrict__ in_b,
                                             const float* __restrict__ cw0) {
    __shared__ __align__(16) float xs[68 * 19];    // also conv red area
    __shared__ __align__(16) float yb[68 * 36];
    __shared__ __align__(16) float wsin[576];
    __shared__ __align__(16) float bsin[32];
    __shared__ __align__(16) float cw[3072];
    int tid = threadIdx.x;
    int fb = blockIdx.x * T_CORE;
    int E = min(T_CORE, F_N - fb);
    size_t rowbase = (size_t)blockIdx.y * F_N;

    for (int idx = tid; idx < (E + 2) * 18; idx += 256) {
        int s = idx / 18, i = idx - s * 18;
        int f = fb - 1 + s;
        xs[s * 19 + i] = (f >= 0 && f < F_N) ? x[(rowbase + f) * 18 + i] : 0.f;
    }
    for (int idx = tid; idx < 576; idx += 256) wsin[idx] = in_w[idx];
    if (tid < 32) bsin[tid] = in_b[tid];
    for (int idx = tid; idx < 3072; idx += 256) cw[idx] = cw0[idx];
    __syncthreads();

    int s = tid;
    if (s < E + 2) {
        int f = fb - 1 + s;
        u64 acc[16];
        if (f >= 0 && f < F_N) {
            const u64* b2 = (const u64*)bsin;
#pragma unroll
            for (int k = 0; k < 16; k++) acc[k] = b2[k];
#pragma unroll
            for (int i = 0; i < 18; i++) {
                u64 a2 = pack2(xs[s * 19 + i]);
                const u64* wr = (const u64*)(wsin + i * 32);
#pragma unroll
                for (int k = 0; k < 16; k++) ffma2(acc[k], a2, wr[k]);
            }
        } else {
#pragma unroll
            for (int k = 0; k < 16; k++) acc[k] = 0ull;
        }
        ulonglong2* o = (ulonglong2*)&yb[s * 36];
#pragma unroll
        for (int k = 0; k < 8; k++) o[k] = make_ulonglong2(acc[2 * k], acc[2 * k + 1]);
    }
    __syncthreads();

    for (int idx = tid; idx < E * 32; idx += 256) {
        int t = idx >> 5, c = idx & 31;
        g_h[0][(rowbase + fb + t) * 32 + c] = yb[(t + 1) * 36 + c];
    }
    conv_phase(yb, cw, fb, E, rowbase, (int)blockIdx.y * NBX + blockIdx.x, xs, g_c[0]);
}

// ===== BN finalize: one block per channel, coalesced =====
__global__ __launch_bounds__(256) void k_bnfin(const float* __restrict__ bng,
                                               const float* __restrict__ bnb) {
    __shared__ float rs[256], rq[256];
    int c = blockIdx.x;
    float s = 0.f, q = 0.f;
    for (int i = threadIdx.x; i < NPART; i += 256) {
        s += g_part[c][i];
        q += g_part[32 + c][i];
    }
    rs[threadIdx.x] = s; rq[threadIdx.x] = q;
    __syncthreads();
    for (int off = 128; off > 0; off >>= 1) {
        if (threadIdx.x < off) {
            rs[threadIdx.x] += rs[threadIdx.x + off];
            rq[threadIdx.x] += rq[threadIdx.x + off];
        }
        __syncthreads();
    }
    if (threadIdx.x == 0) {
        float mean = rs[0] * (1.0f / BF_N);
        float var = rq[0] * (1.0f / BF_N) - mean * mean;
        float a = rsqrtf(var + 1e-5f) * bng[c];
        g_bn[0][c] = a;
        g_bn[1][c] = bnb[c] - mean * a;
    }
}

// ===== fused layer: qkv GEMM + banded attn + proj + BN/GELU + LN(+write) + next-conv =====
// smem floats:
//   R1 [0,2304):        ht [32][72] channel-major -> as_ [67][33] after B -> conv red
//   qs [2304,9504):     stage temp [72][33] -> [72][100] q|k|v -> y [67][36] + cw (at +2412)
//   wq [9504,12576)     32x96
//   wp [12576,13600)    32x32
//   params [13600,13760)
#define SMEM_APPLY (13760 * 4)
__global__ __launch_bounds__(256) void k_apply(const float* __restrict__ qw,
                                               const float* __restrict__ pw,
                                               const float* __restrict__ pbias,
                                               const float* __restrict__ lng,
                                               const float* __restrict__ lnb,
                                               const float* __restrict__ cwn,
                                               int src, int cidx, int last) {
    extern __shared__ float sm[];
    float* R1 = sm;               // ht then as_
    float* qs = sm + 2304;        // temp, then qkv, later y + cw
    float* wq = sm + 9504;
    float* wp = sm + 12576;
    float* pb = sm + 13600;
    float* lg = pb + 32;
    float* lb = lg + 32;
    float* bna = lb + 32;
    float* bnb = bna + 32;

    float* ht = R1;               // [32][72]
    float* as_ = R1;              // [67][33] (after B; ht dead)
    float* y = qs;                // [67][36] (after C; qs rows dead)
    float* cw = qs + 2412;        // 3072 floats

    int tid = threadIdx.x;
    int fb = blockIdx.x * T_CORE;
    int E = min(T_CORE, F_N - fb);
    size_t rowbase = (size_t)blockIdx.y * F_N;
    const float* hsrc = g_h[src];
    float* hdst = g_h[src ^ 1];
    const float* gc_in = g_c[cidx];
    float* gc_out = g_c[cidx ^ 1];

    // ---- stage 1: coalesced LDG token-major into temp [72][33] (in qs region) ----
    float* tmp = qs;
    for (int idx = tid; idx < 72 * 32; idx += 256) {
        int t = idx >> 5, c = idx & 31;
        int f = fb - 1 + t;
        tmp[t * 33 + c] = (f >= 0 && f < F_N) ? hsrc[(rowbase + f) * 32 + c] : 0.f;
    }
    for (int idx = tid; idx < 3072; idx += 256) wq[idx] = qw[idx];
    for (int idx = tid; idx < 1024; idx += 256) wp[idx] = pw[idx];
    if (tid < 32) {
        pb[tid] = pbias[tid]; lg[tid] = lng[tid]; lb[tid] = lnb[tid];
        bna[tid] = g_bn[0][tid]; bnb[tid] = g_bn[1][tid];
    }
    __syncthreads();

    // ---- stage 2: conflict-free smem transpose -> ht [32][72] channel-major ----
    for (int idx = tid; idx < 32 * 72; idx += 256) {
        int c = idx / 72, t = idx - c * 72;
        ht[c * 72 + t] = tmp[t * 33 + c];
    }
    __syncthreads();

    // ---- Phase B: qkv GEMM (72 tok x 96 ch, K=32), 4 tok x 8 ch, FFMA2; 216 units ----
    if (tid < 216) {
        int og = tid / 18, tg = tid - og * 18;
        int t0 = tg * 4, oc = og * 8;
        u64 acc2[4][4];
#pragma unroll
        for (int a = 0; a < 4; a++)
#pragma unroll
            for (int k = 0; k < 4; k++) acc2[a][k] = 0ull;
#pragma unroll
        for (int i = 0; i < 32; i++) {
            float4 av = *reinterpret_cast<const float4*>(&ht[i * 72 + t0]);
            const u64* wr = reinterpret_cast<const u64*>(&wq[i * 96 + oc]);
            u64 w0 = wr[0], w1 = wr[1], w2 = wr[2], w3 = wr[3];
            u64 a0 = pack2(av.x), a1 = pack2(av.y), a2 = pack2(av.z), a3 = pack2(av.w);
            ffma2(acc2[0][0], a0, w0); ffma2(acc2[0][1], a0, w1); ffma2(acc2[0][2], a0, w2); ffma2(acc2[0][3], a0, w3);
            ffma2(acc2[1][0], a1, w0); ffma2(acc2[1][1], a1, w1); ffma2(acc2[1][2], a1, w2); ffma2(acc2[1][3], a1, w3);
            ffma2(acc2[2][0], a2, w0); ffma2(acc2[2][1], a2, w1); ffma2(acc2[2][2], a2, w2); ffma2(acc2[2][3], a2, w3);
            ffma2(acc2[3][0], a3, w0); ffma2(acc2[3][1], a3, w1); ffma2(acc2[3][2], a3, w2); ffma2(acc2[3][3], a3, w3);
        }
#pragma unroll
        for (int a = 0; a < 4; a++) {
            ulonglong2* dst = reinterpret_cast<ulonglong2*>(&qs[(t0 + a) * 100 + oc]);
            dst[0] = make_ulonglong2(acc2[a][0], acc2[a][1]);
            dst[1] = make_ulonglong2(acc2[a][2], acc2[a][3]);
        }
    }
    __syncthreads();

    // ---- Phase C: banded attention, warp per slot (lane=channel) -> as_ (over dead ht) ----
    int warp = tid >> 5, lane = tid & 31;
    for (int rep = 0; rep < 9; rep++) {
        int s = rep * 8 + warp;
        if (s >= 67) break;
        int f = fb - 1 + s;
        if (f >= 0 && f < F_N) {
            float qv = qs[s * 100 + lane];
            float sc[3];
#pragma unroll
            for (int j = 0; j < 3; j++) {
                float p = qv * qs[(s + j) * 100 + 32 + lane];
                p += __shfl_xor_sync(0xffffffffu, p, 1);
                p += __shfl_xor_sync(0xffffffffu, p, 2);
                p += __shfl_xor_sync(0xffffffffu, p, 4);
                sc[j] = (f + j < F_N) ? p * 0.35355339059327373f : -INFINITY;
            }
            float m = fmaxf(sc[0], fmaxf(sc[1], sc[2]));
            float e0 = __expf(sc[0] - m);
            float e1 = (f + 1 < F_N) ? __expf(sc[1] - m) : 0.f;
            float e2 = (f + 2 < F_N) ? __expf(sc[2] - m) : 0.f;
            float inv = 1.f / (e0 + e1 + e2);
            float ao = (e0 * qs[s * 100 + 64 + lane]
                      + e1 * qs[(s + 1) * 100 + 64 + lane]
                      + e2 * qs[(s + 2) * 100 + 64 + lane]) * inv;
            as_[s * 33 + lane] = ao;
        } else {
            as_[s * 33 + lane] = 0.f;
        }
    }
    __syncthreads();

    // qs rows dead: overlay next-layer conv weights (disjoint from y region)
    if (!last)
        for (int idx = tid; idx < 3072; idx += 256) cw[idx] = cwn[idx];

    // ---- Phase D: proj + BN(c)/GELU + residual + LayerNorm + global write -> y ----
    // 268 (s, o0) units over 2 uniform passes; 4 threads share one token -> LN via 2 xor-shfls.
#pragma unroll
    for (int p = 0; p < 2; p++) {
        int sl = tid + p * 256;
        bool valid = sl < 268;
        int s = valid ? (sl >> 2) : 0;
        int o0 = (sl & 3) << 3;
        int f = fb - 1 + s;
        bool fv = valid && f >= 0 && f < F_N;
        float yv[8];
        if (fv) {
            u64 acc2[4];
            const u64* pb2 = (const u64*)(pb + o0);
            acc2[0] = pb2[0]; acc2[1] = pb2[1]; acc2[2] = pb2[2]; acc2[3] = pb2[3];
#pragma unroll
            for (int i = 0; i < 32; i++) {
                u64 a2 = pack2(as_[s * 33 + i]);
                const u64* wr = (const u64*)(wp + i * 32 + o0);
                ffma2(acc2[0], a2, wr[0]);
                ffma2(acc2[1], a2, wr[1]);
                ffma2(acc2[2], a2, wr[2]);
                ffma2(acc2[3], a2, wr[3]);
            }
            const float4* cg = (const float4*)&gc_in[(rowbase + f) * 32 + o0];
            float4 c0 = cg[0], c1 = cg[1];
            float cv[8] = {c0.x, c0.y, c0.z, c0.w, c1.x, c1.y, c1.z, c1.w};
#pragma unroll
            for (int k = 0; k < 4; k++) {
                float2 pa = unpack2(acc2[k]);
                float cn0 = cv[2 * k] * bna[o0 + 2 * k] + bnb[o0 + 2 * k];
                float cn1 = cv[2 * k + 1] * bna[o0 + 2 * k + 1] + bnb[o0 + 2 * k + 1];
                yv[2 * k] = gelu_f(cn0) + pa.x;
                yv[2 * k + 1] = gelu_f(cn1) + pa.y;
            }
        } else {
#pragma unroll
            for (int j = 0; j < 8; j++) yv[j] = 0.f;
        }
        // LayerNorm across the 4 threads of this token (uniform shfl execution)
        float ls = 0.f, lq = 0.f;
#pragma unroll
        for (int j = 0; j < 8; j++) { ls += yv[j]; lq += yv[j] * yv[j]; }
        ls += __shfl_xor_sync(0xffffffffu, ls, 1);
        ls += __shfl_xor_sync(0xffffffffu, ls, 2);
        lq += __shfl_xor_sync(0xffffffffu, lq, 1);
        lq += __shfl_xor_sync(0xffffffffu, lq, 2);
        float mean = ls * (1.f / 32.f);
        float var = lq * (1.f / 32.f) - mean * mean;
        float rstd = rsqrtf(var + 1e-5f);
        float ov[8];
#pragma unroll
        for (int j = 0; j < 8; j++)
            ov[j] = (yv[j] - mean) * rstd * lg[o0 + j] + lb[o0 + j];
        if (fv) {
            float4* yo = (float4*)&y[s * 36 + o0];
            yo[0] = make_float4(ov[0], ov[1], ov[2], ov[3]);
            yo[1] = make_float4(ov[4], ov[5], ov[6], ov[7]);
            if (s >= 1 && s <= E) {
                float4* ho = (float4*)&hdst[(rowbase + f) * 32 + o0];
                ho[0] = make_float4(ov[0], ov[1], ov[2], ov[3]);
                ho[1] = make_float4(ov[4], ov[5], ov[6], ov[7]);
            }
        }
    }
    if (last) return;
    __syncthreads();

    // ---- fused next-layer conv on smem y ----
    conv_phase(y, cw, fb, E, rowbase, (int)blockIdx.y * NBX + blockIdx.x, R1, gc_out);
}

// ===== head: gelu(h@W1+b1) @ W2 + b2 -> sigmoid =====
__global__ __launch_bounds__(256) void k_head(const float* __restrict__ w1,
                                              const float* __restrict__ b1,
                                              const float* __restrict__ w2,
                                              const float* __restrict__ b2,
                                              float* __restrict__ out) {
    __shared__ __align__(16) float hsm[256][33];
    __shared__ __align__(16) float ws1[512];
    __shared__ __align__(16) float wb1[16];
    __shared__ __align__(16) float ws2[16];
    __shared__ float b2s;
    int t0 = blockIdx.x * 256;
    const float* hsrc = g_h[0];
    for (int idx = threadIdx.x; idx < 256 * 32; idx += 256) {
        int tok = idx >> 5, c = idx & 31;
        hsm[tok][c] = hsrc[(size_t)(t0 + tok) * 32 + c];
    }
    for (int idx = threadIdx.x; idx < 512; idx += 256) ws1[idx] = w1[idx];
    if (threadIdx.x < 16) { wb1[threadIdx.x] = b1[threadIdx.x]; ws2[threadIdx.x] = w2[threadIdx.x]; }
    if (threadIdx.x == 0) b2s = b2[0];
    __syncthreads();

    const float* hr = hsm[threadIdx.x];
    u64 s2[8];
    const u64* wb2 = (const u64*)wb1;
#pragma unroll
    for (int k = 0; k < 8; k++) s2[k] = wb2[k];
#pragma unroll
    for (int i = 0; i < 32; i++) {
        u64 a2 = pack2(hr[i]);
        const u64* wr = (const u64*)(ws1 + i * 16);
#pragma unroll
        for (int k = 0; k < 8; k++) ffma2(s2[k], a2, wr[k]);
    }
    float m = b2s;
#pragma unroll
    for (int k = 0; k < 8; k++) {
        float2 f2 = unpack2(s2[k]);
        m += gelu_f(f2.x) * ws2[2 * k] + gelu_f(f2.y) * ws2[2 * k + 1];
    }
    out[t0 + threadIdx.x] = 1.f / (1.f + expf(-m));
}

// ===== launcher =====
extern "C" void kernel_launch(void* const* d_in, const int* in_sizes, int n_in,
                              void* d_out, int out_size) {
    const float* x      = (const float*)d_in[0];
    const float* in_w   = (const float*)d_in[1];
    const float* in_b   = (const float*)d_in[2];
    const float* conv_w = (const float*)d_in[3];
    const float* bn_g   = (const float*)d_in[4];
    const float* bn_b   = (const float*)d_in[5];
    const float* qkv_w  = (const float*)d_in[6];
    const float* proj_w = (const float*)d_in[7];
    const float* proj_b = (const float*)d_in[8];
    const float* ln_g   = (const float*)d_in[9];
    const float* ln_b   = (const float*)d_in[10];
    const float* h1_w   = (const float*)d_in[11];
    const float* h1_b   = (const float*)d_in[12];
    const float* h2_w   = (const float*)d_in[13];
    const float* h2_b   = (const float*)d_in[14];
    float* out = (float*)d_out;

    cudaFuncSetAttribute(k_apply, cudaFuncAttributeMaxDynamicSharedMemorySize, SMEM_APPLY);

    dim3 grid(NBX, B_N);
    k_pre<<<grid, 256>>>(x, in_w, in_b, conv_w);
    for (int l = 0; l < 4; l++) {
        int src = l & 1;
        int cidx = l & 1;   // layer l reads g_c[l&1], writes g_c[(l&1)^1]
        int last = (l == 3) ? 1 : 0;
        k_bnfin<<<32, 256>>>(bn_g + l * 32, bn_b + l * 32);
        k_apply<<<grid, 256, SMEM_APPLY>>>(qkv_w + l * 3072, proj_w + l * 1024,
                                           proj_b + l * 32, ln_g + l * 32, ln_b + l * 32,
                                           conv_w + (l + 1 < 4 ? l + 1 : 0) * 3072,
                                           src, cidx, last);
    }
    k_head<<<BF_N / 256, 256>>>(h1_w, h1_b, h2_w, h2_b, out);
}

// round 9
// speedup vs baseline: 2.2362x; 1.0212x over previous
#include <cuda_runtime.h>
#include <math.h>

#define B_N 1024
#define F_N 257
#define BF_N (B_N * F_N)
#define T_CORE 65
#define NBX 4
#define NPART (NBX * B_N)   // 4096

typedef unsigned long long u64;

// -------- device scratch (allocation-free) --------
__device__ __align__(16) float g_h[2][(size_t)BF_N * 32];
__device__ __align__(16) float g_c[2][(size_t)BF_N * 32];   // ping-pong per layer
__device__ __align__(16) float g_part[64][NPART];           // [kind*32+ch][block]
__device__ __align__(16) float g_bn[2][32];

__device__ __forceinline__ float gelu_f(float x) {
    return 0.5f * x * (1.0f + erff(x * 0.70710678118654752440f));
}
__device__ __forceinline__ void ffma2(u64& d, u64 a, u64 b) {
    asm("fma.rn.f32x2 %0, %1, %2, %0;" : "+l"(d) : "l"(a), "l"(b));
}
__device__ __forceinline__ u64 pack2(float x) {
    u64 r; asm("mov.b64 %0, {%1, %1};" : "=l"(r) : "f"(x)); return r;
}
__device__ __forceinline__ float2 unpack2(u64 a) {
    float2 f; asm("mov.b64 {%0, %1}, %2;" : "=f"(f.x), "=f"(f.y) : "l"(a)); return f;
}

// ===== conv (width-3 over F) on smem y [.][36] + BN partials; ALL 256 threads call =====
// y rows are 16B-aligned (36 floats = 144B) -> float4 activation reads.
__device__ __forceinline__ void conv_phase(const float* y, const float* cws,
                                           int fb, int E, size_t rowbase,
                                           int pidx, float* red, float* gc_out) {
    int tid = threadIdx.x;
    int tq = tid >> 2, o0 = (tid & 3) << 3;
    float s1[8], s2[8];
#pragma unroll
    for (int j = 0; j < 8; j++) { s1[j] = 0.f; s2[j] = 0.f; }
#pragma unroll
    for (int it = 0; it < 2; it++) {
        int t = it * 64 + tq;
        if (t < E) {
            int f = fb + t;
            int s = t + 1;  // y slot for global token f
            u64 acc2[4] = {0ull, 0ull, 0ull, 0ull};
#pragma unroll
            for (int w = 0; w < 3; w++) {
                if (w == 0 && f == 0) continue;
                if (w == 2 && f == F_N - 1) continue;
                const float4* yr4 = (const float4*)(y + (s - 1 + w) * 36);
                const float* wb = cws + w * 1024 + o0;
#pragma unroll
                for (int i4 = 0; i4 < 8; i4++) {
                    float4 v = yr4[i4];
                    u64 a0 = pack2(v.x), a1 = pack2(v.y), a2 = pack2(v.z), a3 = pack2(v.w);
                    const u64* w0 = (const u64*)(wb + (4 * i4 + 0) * 32);
                    const u64* w1 = (const u64*)(wb + (4 * i4 + 1) * 32);
                    const u64* w2 = (const u64*)(wb + (4 * i4 + 2) * 32);
                    const u64* w3 = (const u64*)(wb + (4 * i4 + 3) * 32);
                    ffma2(acc2[0], a0, w0[0]); ffma2(acc2[1], a0, w0[1]); ffma2(acc2[2], a0, w0[2]); ffma2(acc2[3], a0, w0[3]);
                    ffma2(acc2[0], a1, w1[0]); ffma2(acc2[1], a1, w1[1]); ffma2(acc2[2], a1, w1[2]); ffma2(acc2[3], a1, w1[3]);
                    ffma2(acc2[0], a2, w2[0]); ffma2(acc2[1], a2, w2[1]); ffma2(acc2[2], a2, w2[2]); ffma2(acc2[3], a2, w2[3]);
                    ffma2(acc2[0], a3, w3[0]); ffma2(acc2[1], a3, w3[1]); ffma2(acc2[2], a3, w3[2]); ffma2(acc2[3], a3, w3[3]);
                }
            }
            ulonglong2* co = (ulonglong2*)&gc_out[(rowbase + f) * 32 + o0];
            co[0] = make_ulonglong2(acc2[0], acc2[1]);
            co[1] = make_ulonglong2(acc2[2], acc2[3]);
#pragma unroll
            for (int k = 0; k < 4; k++) {
                float2 f2 = unpack2(acc2[k]);
                s1[2 * k] += f2.x;     s2[2 * k] += f2.x * f2.x;
                s1[2 * k + 1] += f2.y; s2[2 * k + 1] += f2.y * f2.y;
            }
        }
    }
#pragma unroll
    for (int off = 4; off < 32; off <<= 1) {
#pragma unroll
        for (int j = 0; j < 8; j++) {
            s1[j] += __shfl_xor_sync(0xffffffffu, s1[j], off);
            s2[j] += __shfl_xor_sync(0xffffffffu, s2[j], off);
        }
    }
    int warp = tid >> 5, lane = tid & 31;
    if (lane < 4) {
#pragma unroll
        for (int j = 0; j < 8; j++) {
            red[((warp * 4 + lane) * 8 + j) * 2 + 0] = s1[j];
            red[((warp * 4 + lane) * 8 + j) * 2 + 1] = s2[j];
        }
    }
    __syncthreads();
    if (tid < 64) {
        int kind = tid >> 5, ch = tid & 31;
        int sl = ch >> 3, j = ch & 7;
        float v = 0.f;
#pragma unroll
        for (int w2 = 0; w2 < 8; w2++) v += red[((w2 * 4 + sl) * 8 + j) * 2 + kind];
        g_part[kind * 32 + ch][pidx] = v;
    }
}

// ===== k_pre: inproj (18->32) + conv layer-0 + partials =====
__global__ __launch_bounds__(256) void k_pre(const float* __restrict__ x,
                                             const float* __restrict__ in_w,
                                             const float* __restrict__ in_b,
                                             const float* __restrict__ cw0) {
    __shared__ __align__(16) float xs[68 * 19];    // also conv red area
    __shared__ __align__(16) float yb[68 * 36];
    __shared__ __align__(16) float wsin[576];
    __shared__ __align__(16) float bsin[32];
    __shared__ __align__(16) float cw[3072];
    int tid = threadIdx.x;
    int fb = blockIdx.x * T_CORE;
    int E = min(T_CORE, F_N - fb);
    size_t rowbase = (size_t)blockIdx.y * F_N;

    for (int idx = tid; idx < (E + 2) * 18; idx += 256) {
        int s = idx / 18, i = idx - s * 18;
        int f = fb - 1 + s;
        xs[s * 19 + i] = (f >= 0 && f < F_N) ? x[(rowbase + f) * 18 + i] : 0.f;
    }
    for (int idx = tid; idx < 576; idx += 256) wsin[idx] = in_w[idx];
    if (tid < 32) bsin[tid] = in_b[tid];
    for (int idx = tid; idx < 3072; idx += 256) cw[idx] = cw0[idx];
    __syncthreads();

    int s = tid;
    if (s < E + 2) {
        int f = fb - 1 + s;
        u64 acc[16];
        if (f >= 0 && f < F_N) {
            const u64* b2 = (const u64*)bsin;
#pragma unroll
            for (int k = 0; k < 16; k++) acc[k] = b2[k];
#pragma unroll
            for (int i = 0; i < 18; i++) {
                u64 a2 = pack2(xs[s * 19 + i]);
                const u64* wr = (const u64*)(wsin + i * 32);
#pragma unroll
                for (int k = 0; k < 16; k++) ffma2(acc[k], a2, wr[k]);
            }
        } else {
#pragma unroll
            for (int k = 0; k < 16; k++) acc[k] = 0ull;
        }
        ulonglong2* o = (ulonglong2*)&yb[s * 36];
#pragma unroll
        for (int k = 0; k < 8; k++) o[k] = make_ulonglong2(acc[2 * k], acc[2 * k + 1]);
    }
    __syncthreads();

    for (int idx = tid; idx < E * 32; idx += 256) {
        int t = idx >> 5, c = idx & 31;
        g_h[0][(rowbase + fb + t) * 32 + c] = yb[(t + 1) * 36 + c];
    }
    conv_phase(yb, cw, fb, E, rowbase, (int)blockIdx.y * NBX + blockIdx.x, xs, g_c[0]);
}

// ===== BN finalize: one block per channel, coalesced + vectorized =====
__global__ __launch_bounds__(256) void k_bnfin(const float* __restrict__ bng,
                                               const float* __restrict__ bnb) {
    __shared__ float rs[256], rq[256];
    int c = blockIdx.x;
    float s = 0.f, q = 0.f;
    const float4* pr = (const float4*)g_part[c];
    const float4* qr = (const float4*)g_part[32 + c];
    for (int i = threadIdx.x; i < NPART / 4; i += 256) {
        float4 a = pr[i]; s += a.x + a.y + a.z + a.w;
        float4 b = qr[i]; q += b.x + b.y + b.z + b.w;
    }
    rs[threadIdx.x] = s; rq[threadIdx.x] = q;
    __syncthreads();
    for (int off = 128; off > 0; off >>= 1) {
        if (threadIdx.x < off) {
            rs[threadIdx.x] += rs[threadIdx.x + off];
            rq[threadIdx.x] += rq[threadIdx.x + off];
        }
        __syncthreads();
    }
    if (threadIdx.x == 0) {
        float mean = rs[0] * (1.0f / BF_N);
        float var = rq[0] * (1.0f / BF_N) - mean * mean;
        float a = rsqrtf(var + 1e-5f) * bng[c];
        g_bn[0][c] = a;
        g_bn[1][c] = bnb[c] - mean * a;
    }
}

// ===== fused layer: qkv GEMM + banded attn + proj + BN/GELU + LN(+write) + next-conv =====
// smem floats:
//   R1 [0,2304):        ht [32][72] channel-major -> as_ [67][34] (2278) after B -> conv red
//   qs [2304,9504):     stage temp [72][33] -> [72][100] q|k|v -> y [67][36] + cw (at +2412)
//   wq [9504,12576)     32x96
//   wp [12576,13600)    32x32
//   params [13600,13760)
#define SMEM_APPLY (13760 * 4)
__global__ __launch_bounds__(256) void k_apply(const float* __restrict__ qw,
                                               const float* __restrict__ pw,
                                               const float* __restrict__ pbias,
                                               const float* __restrict__ lng,
                                               const float* __restrict__ lnb,
                                               const float* __restrict__ cwn,
                                               int src, int cidx, int last) {
    extern __shared__ float sm[];
    float* R1 = sm;               // ht then as_
    float* qs = sm + 2304;        // temp, then qkv, later y + cw
    float* wq = sm + 9504;
    float* wp = sm + 12576;
    float* pb = sm + 13600;
    float* lg = pb + 32;
    float* lb = lg + 32;
    float* bna = lb + 32;
    float* bnb = bna + 32;

    float* ht = R1;               // [32][72]
    float* as_ = R1;              // [67][34] (after B; ht dead); 8B-aligned rows
    float* y = qs;                // [67][36] (after C; qs rows dead)
    float* cw = qs + 2412;        // 3072 floats

    int tid = threadIdx.x;
    int fb = blockIdx.x * T_CORE;
    int E = min(T_CORE, F_N - fb);
    size_t rowbase = (size_t)blockIdx.y * F_N;
    const float* hsrc = g_h[src];
    float* hdst = g_h[src ^ 1];
    const float* gc_in = g_c[cidx];
    float* gc_out = g_c[cidx ^ 1];

    // ---- stage 1: coalesced LDG token-major into temp [72][33] (in qs region) ----
    float* tmp = qs;
    for (int idx = tid; idx < 72 * 32; idx += 256) {
        int t = idx >> 5, c = idx & 31;
        int f = fb - 1 + t;
        tmp[t * 33 + c] = (f >= 0 && f < F_N) ? hsrc[(rowbase + f) * 32 + c] : 0.f;
    }
    for (int idx = tid; idx < 3072; idx += 256) wq[idx] = qw[idx];
    for (int idx = tid; idx < 1024; idx += 256) wp[idx] = pw[idx];
    if (tid < 32) {
        pb[tid] = pbias[tid]; lg[tid] = lng[tid]; lb[tid] = lnb[tid];
        bna[tid] = g_bn[0][tid]; bnb[tid] = g_bn[1][tid];
    }
    __syncthreads();

    // ---- stage 2: conflict-free smem transpose -> ht [32][72] channel-major ----
    for (int idx = tid; idx < 32 * 72; idx += 256) {
        int c = idx / 72, t = idx - c * 72;
        ht[c * 72 + t] = tmp[t * 33 + c];
    }
    __syncthreads();

    // ---- Phase B: qkv GEMM (72 tok x 96 ch, K=32), 4 tok x 8 ch, FFMA2; 216 units ----
    if (tid < 216) {
        int og = tid / 18, tg = tid - og * 18;
        int t0 = tg * 4, oc = og * 8;
        u64 acc2[4][4];
#pragma unroll
        for (int a = 0; a < 4; a++)
#pragma unroll
            for (int k = 0; k < 4; k++) acc2[a][k] = 0ull;
#pragma unroll
        for (int i = 0; i < 32; i++) {
            float4 av = *reinterpret_cast<const float4*>(&ht[i * 72 + t0]);
            const u64* wr = reinterpret_cast<const u64*>(&wq[i * 96 + oc]);
            u64 w0 = wr[0], w1 = wr[1], w2 = wr[2], w3 = wr[3];
            u64 a0 = pack2(av.x), a1 = pack2(av.y), a2 = pack2(av.z), a3 = pack2(av.w);
            ffma2(acc2[0][0], a0, w0); ffma2(acc2[0][1], a0, w1); ffma2(acc2[0][2], a0, w2); ffma2(acc2[0][3], a0, w3);
            ffma2(acc2[1][0], a1, w0); ffma2(acc2[1][1], a1, w1); ffma2(acc2[1][2], a1, w2); ffma2(acc2[1][3], a1, w3);
            ffma2(acc2[2][0], a2, w0); ffma2(acc2[2][1], a2, w1); ffma2(acc2[2][2], a2, w2); ffma2(acc2[2][3], a2, w3);
            ffma2(acc2[3][0], a3, w0); ffma2(acc2[3][1], a3, w1); ffma2(acc2[3][2], a3, w2); ffma2(acc2[3][3], a3, w3);
        }
#pragma unroll
        for (int a = 0; a < 4; a++) {
            ulonglong2* dst = reinterpret_cast<ulonglong2*>(&qs[(t0 + a) * 100 + oc]);
            dst[0] = make_ulonglong2(acc2[a][0], acc2[a][1]);
            dst[1] = make_ulonglong2(acc2[a][2], acc2[a][3]);
        }
    }
    __syncthreads();

    // ---- Phase C: banded attention, warp per slot (lane=channel) -> as_ (over dead ht) ----
    int warp = tid >> 5, lane = tid & 31;
    for (int rep = 0; rep < 9; rep++) {
        int s = rep * 8 + warp;
        if (s >= 67) break;
        int f = fb - 1 + s;
        if (f >= 0 && f < F_N) {
            float qv = qs[s * 100 + lane];
            float sc[3];
#pragma unroll
            for (int j = 0; j < 3; j++) {
                float p = qv * qs[(s + j) * 100 + 32 + lane];
                p += __shfl_xor_sync(0xffffffffu, p, 1);
                p += __shfl_xor_sync(0xffffffffu, p, 2);
                p += __shfl_xor_sync(0xffffffffu, p, 4);
                sc[j] = (f + j < F_N) ? p * 0.35355339059327373f : -INFINITY;
            }
            float m = fmaxf(sc[0], fmaxf(sc[1], sc[2]));
            float e0 = __expf(sc[0] - m);
            float e1 = (f + 1 < F_N) ? __expf(sc[1] - m) : 0.f;
            float e2 = (f + 2 < F_N) ? __expf(sc[2] - m) : 0.f;
            float inv = 1.f / (e0 + e1 + e2);
            float ao = (e0 * qs[s * 100 + 64 + lane]
                      + e1 * qs[(s + 1) * 100 + 64 + lane]
                      + e2 * qs[(s + 2) * 100 + 64 + lane]) * inv;
            as_[s * 34 + lane] = ao;
        } else {
            as_[s * 34 + lane] = 0.f;
        }
    }
    __syncthreads();

    // qs rows dead: overlay next-layer conv weights (disjoint from y region)
    if (!last)
        for (int idx = tid; idx < 3072; idx += 256) cw[idx] = cwn[idx];

    // ---- Phase D: proj + BN(c)/GELU + residual + LayerNorm + global write -> y ----
#pragma unroll
    for (int p = 0; p < 2; p++) {
        int sl = tid + p * 256;
        bool valid = sl < 268;
        int s = valid ? (sl >> 2) : 0;
        int o0 = (sl & 3) << 3;
        int f = fb - 1 + s;
        bool fv = valid && f >= 0 && f < F_N;
        float yv[8];
        if (fv) {
            u64 acc2[4];
            const u64* pb2 = (const u64*)(pb + o0);
            acc2[0] = pb2[0]; acc2[1] = pb2[1]; acc2[2] = pb2[2]; acc2[3] = pb2[3];
            const u64* ar = (const u64*)(as_ + s * 34);   // 8B-aligned (s*136 bytes)
#pragma unroll
            for (int i2 = 0; i2 < 16; i2++) {
                float2 aa = unpack2(ar[i2]);
                u64 a0 = pack2(aa.x), a1 = pack2(aa.y);
                const u64* w0 = (const u64*)(wp + (2 * i2) * 32 + o0);
                const u64* w1 = (const u64*)(wp + (2 * i2 + 1) * 32 + o0);
                ffma2(acc2[0], a0, w0[0]); ffma2(acc2[1], a0, w0[1]);
                ffma2(acc2[2], a0, w0[2]); ffma2(acc2[3], a0, w0[3]);
                ffma2(acc2[0], a1, w1[0]); ffma2(acc2[1], a1, w1[1]);
                ffma2(acc2[2], a1, w1[2]); ffma2(acc2[3], a1, w1[3]);
            }
            const float4* cg = (const float4*)&gc_in[(rowbase + f) * 32 + o0];
            float4 c0 = cg[0], c1 = cg[1];
            float cv[8] = {c0.x, c0.y, c0.z, c0.w, c1.x, c1.y, c1.z, c1.w};
#pragma unroll
            for (int k = 0; k < 4; k++) {
                float2 pa = unpack2(acc2[k]);
                float cn0 = cv[2 * k] * bna[o0 + 2 * k] + bnb[o0 + 2 * k];
                float cn1 = cv[2 * k + 1] * bna[o0 + 2 * k + 1] + bnb[o0 + 2 * k + 1];
                yv[2 * k] = gelu_f(cn0) + pa.x;
                yv[2 * k + 1] = gelu_f(cn1) + pa.y;
            }
        } else {
#pragma unroll
            for (int j = 0; j < 8; j++) yv[j] = 0.f;
        }
        // LayerNorm across the 4 threads of this token (uniform shfl execution)
        float ls = 0.f, lq = 0.f;
#pragma unroll
        for (int j = 0; j < 8; j++) { ls += yv[j]; lq += yv[j] * yv[j]; }
        ls += __shfl_xor_sync(0xffffffffu, ls, 1);
        ls += __shfl_xor_sync(0xffffffffu, ls, 2);
        lq += __shfl_xor_sync(0xffffffffu, lq, 1);
        lq += __shfl_xor_sync(0xffffffffu, lq, 2);
        float mean = ls * (1.f / 32.f);
        float var = lq * (1.f / 32.f) - mean * mean;
        float rstd = rsqrtf(var + 1e-5f);
        float ov[8];
#pragma unroll
        for (int j = 0; j < 8; j++)
            ov[j] = (yv[j] - mean) * rstd * lg[o0 + j] + lb[o0 + j];
        if (fv) {
            float4* yo = (float4*)&y[s * 36 + o0];
            yo[0] = make_float4(ov[0], ov[1], ov[2], ov[3]);
            yo[1] = make_float4(ov[4], ov[5], ov[6], ov[7]);
            if (s >= 1 && s <= E) {
                float4* ho = (float4*)&hdst[(rowbase + f) * 32 + o0];
                ho[0] = make_float4(ov[0], ov[1], ov[2], ov[3]);
                ho[1] = make_float4(ov[4], ov[5], ov[6], ov[7]);
            }
        }
    }
    if (last) return;
    __syncthreads();

    // ---- fused next-layer conv on smem y ----
    conv_phase(y, cw, fb, E, rowbase, (int)blockIdx.y * NBX + blockIdx.x, R1, gc_out);
}

// ===== head: gelu(h@W1+b1) @ W2 + b2 -> sigmoid =====
__global__ __launch_bounds__(256) void k_head(const float* __restrict__ w1,
                                              const float* __restrict__ b1,
                                              const float* __restrict__ w2,
                                              const float* __restrict__ b2,
                                              float* __restrict__ out) {
    __shared__ __align__(16) float hsm[256][33];
    __shared__ __align__(16) float ws1[512];
    __shared__ __align__(16) float wb1[16];
    __shared__ __align__(16) float ws2[16];
    __shared__ float b2s;
    int t0 = blockIdx.x * 256;
    const float* hsrc = g_h[0];
    for (int idx = threadIdx.x; idx < 256 * 32; idx += 256) {
        int tok = idx >> 5, c = idx & 31;
        hsm[tok][c] = hsrc[(size_t)(t0 + tok) * 32 + c];
    }
    for (int idx = threadIdx.x; idx < 512; idx += 256) ws1[idx] = w1[idx];
    if (threadIdx.x < 16) { wb1[threadIdx.x] = b1[threadIdx.x]; ws2[threadIdx.x] = w2[threadIdx.x]; }
    if (threadIdx.x == 0) b2s = b2[0];
    __syncthreads();

    const float* hr = hsm[threadIdx.x];
    u64 s2[8];
    const u64* wb2 = (const u64*)wb1;
#pragma unroll
    for (int k = 0; k < 8; k++) s2[k] = wb2[k];
#pragma unroll
    for (int i = 0; i < 32; i++) {
        u64 a2 = pack2(hr[i]);
        const u64* wr = (const u64*)(ws1 + i * 16);
#pragma unroll
        for (int k = 0; k < 8; k++) ffma2(s2[k], a2, wr[k]);
    }
    float m = b2s;
#pragma unroll
    for (int k = 0; k < 8; k++) {
        float2 f2 = unpack2(s2[k]);
        m += gelu_f(f2.x) * ws2[2 * k] + gelu_f(f2.y) * ws2[2 * k + 1];
    }
    out[t0 + threadIdx.x] = 1.f / (1.f + expf(-m));
}

// ===== launcher =====
extern "C" void kernel_launch(void* const* d_in, const int* in_sizes, int n_in,
                              void* d_out, int out_size) {
    const float* x      = (const float*)d_in[0];
    const float* in_w   = (const float*)d_in[1];
    const float* in_b   = (const float*)d_in[2];
    const float* conv_w = (const float*)d_in[3];
    const float* bn_g   = (const float*)d_in[4];
    const float* bn_b   = (const float*)d_in[5];
    const float* qkv_w  = (const float*)d_in[6];
    const float* proj_w = (const float*)d_in[7];
    const float* proj_b = (const float*)d_in[8];
    const float* ln_g   = (const float*)d_in[9];
    const float* ln_b   = (const float*)d_in[10];
    const float* h1_w   = (const float*)d_in[11];
    const float* h1_b   = (const float*)d_in[12];
    const float* h2_w   = (const float*)d_in[13];
    const float* h2_b   = (const float*)d_in[14];
    float* out = (float*)d_out;

    cudaFuncSetAttribute(k_apply, cudaFuncAttributeMaxDynamicSharedMemorySize, SMEM_APPLY);

    dim3 grid(NBX, B_N);
    k_pre<<<grid, 256>>>(x, in_w, in_b, conv_w);
    for (int l = 0; l < 4; l++) {
        int src = l & 1;
        int cidx = l & 1;   // layer l reads g_c[l&1], writes g_c[(l&1)^1]
        int last = (l == 3) ? 1 : 0;
        k_bnfin<<<32, 256>>>(bn_g + l * 32, bn_b + l * 32);
        k_apply<<<grid, 256, SMEM_APPLY>>>(qkv_w + l * 3072, proj_w + l * 1024,
                                           proj_b + l * 32, ln_g + l * 32, ln_b + l * 32,
                                           conv_w + (l + 1 < 4 ? l + 1 : 0) * 3072,
                                           src, cidx, last);
    }
    k_head<<<BF_N / 256, 256>>>(h1_w, h1_b, h2_w, h2_b, out);
}

// round 11
// speedup vs baseline: 2.2947x; 1.0261x over previous
#include <cuda_runtime.h>
#include <math.h>

#define B_N 1024
#define F_N 257
#define BF_N (B_N * F_N)
#define T_CORE 65
#define NBX 4
#define NPART (NBX * B_N)   // 4096
#define NTH 288             // 9 warps

typedef unsigned long long u64;

// -------- device scratch (allocation-free) --------
__device__ __align__(16) float g_h[2][(size_t)BF_N * 32];
__device__ __align__(16) float g_c[2][(size_t)BF_N * 32];   // ping-pong per layer
__device__ __align__(16) float g_part[64][NPART];           // [kind*32+ch][block]
__device__ __align__(16) float g_bn[2][32];

__device__ __forceinline__ float gelu_f(float x) {
    return 0.5f * x * (1.0f + erff(x * 0.70710678118654752440f));
}
__device__ __forceinline__ void ffma2(u64& d, u64 a, u64 b) {
    asm("fma.rn.f32x2 %0, %1, %2, %0;" : "+l"(d) : "l"(a), "l"(b));
}
__device__ __forceinline__ u64 pack2(float x) {
    u64 r; asm("mov.b64 %0, {%1, %1};" : "=l"(r) : "f"(x)); return r;
}
__device__ __forceinline__ float2 unpack2(u64 a) {
    float2 f; asm("mov.b64 {%0, %1}, %2;" : "=f"(f.x), "=f"(f.y) : "l"(a)); return f;
}

// ===== conv (width-3 over F) on smem y [.][36] + BN partials; ALL NTH threads call =====
// Single pass: tq = tid>>2 in [0,72) covers all 65 core tokens.
__device__ __forceinline__ void conv_phase(const float* y, const float* cws,
                                           int fb, int E, size_t rowbase,
                                           int pidx, float* red, float* gc_out) {
    int tid = threadIdx.x;
    int t = tid >> 2, o0 = (tid & 3) << 3;
    float s1[8], s2[8];
#pragma unroll
    for (int j = 0; j < 8; j++) { s1[j] = 0.f; s2[j] = 0.f; }
    if (t < E) {
        int f = fb + t;
        int s = t + 1;  // y slot for global token f
        u64 acc2[4] = {0ull, 0ull, 0ull, 0ull};
#pragma unroll
        for (int w = 0; w < 3; w++) {
            if (w == 0 && f == 0) continue;
            if (w == 2 && f == F_N - 1) continue;
            const float4* yr4 = (const float4*)(y + (s - 1 + w) * 36);
            const float* wb = cws + w * 1024 + o0;
#pragma unroll
            for (int i4 = 0; i4 < 8; i4++) {
                float4 v = yr4[i4];
                u64 a0 = pack2(v.x), a1 = pack2(v.y), a2 = pack2(v.z), a3 = pack2(v.w);
                const u64* w0 = (const u64*)(wb + (4 * i4 + 0) * 32);
                const u64* w1 = (const u64*)(wb + (4 * i4 + 1) * 32);
                const u64* w2 = (const u64*)(wb + (4 * i4 + 2) * 32);
                const u64* w3 = (const u64*)(wb + (4 * i4 + 3) * 32);
                ffma2(acc2[0], a0, w0[0]); ffma2(acc2[1], a0, w0[1]); ffma2(acc2[2], a0, w0[2]); ffma2(acc2[3], a0, w0[3]);
                ffma2(acc2[0], a1, w1[0]); ffma2(acc2[1], a1, w1[1]); ffma2(acc2[2], a1, w1[2]); ffma2(acc2[3], a1, w1[3]);
                ffma2(acc2[0], a2, w2[0]); ffma2(acc2[1], a2, w2[1]); ffma2(acc2[2], a2, w2[2]); ffma2(acc2[3], a2, w2[3]);
                ffma2(acc2[0], a3, w3[0]); ffma2(acc2[1], a3, w3[1]); ffma2(acc2[2], a3, w3[2]); ffma2(acc2[3], a3, w3[3]);
            }
        }
        ulonglong2* co = (ulonglong2*)&gc_out[(rowbase + f) * 32 + o0];
        co[0] = make_ulonglong2(acc2[0], acc2[1]);
        co[1] = make_ulonglong2(acc2[2], acc2[3]);
#pragma unroll
        for (int k = 0; k < 4; k++) {
            float2 f2 = unpack2(acc2[k]);
            s1[2 * k] += f2.x;     s2[2 * k] += f2.x * f2.x;
            s1[2 * k + 1] += f2.y; s2[2 * k + 1] += f2.y * f2.y;
        }
    }
#pragma unroll
    for (int off = 4; off < 32; off <<= 1) {
#pragma unroll
        for (int j = 0; j < 8; j++) {
            s1[j] += __shfl_xor_sync(0xffffffffu, s1[j], off);
            s2[j] += __shfl_xor_sync(0xffffffffu, s2[j], off);
        }
    }
    int warp = tid >> 5, lane = tid & 31;
    if (lane < 4) {
#pragma unroll
        for (int j = 0; j < 8; j++) {
            red[((warp * 4 + lane) * 8 + j) * 2 + 0] = s1[j];
            red[((warp * 4 + lane) * 8 + j) * 2 + 1] = s2[j];
        }
    }
    __syncthreads();
    if (tid < 64) {
        int kind = tid >> 5, ch = tid & 31;
        int sl = ch >> 3, j = ch & 7;
        float v = 0.f;
#pragma unroll
        for (int w2 = 0; w2 < 9; w2++) v += red[((w2 * 4 + sl) * 8 + j) * 2 + kind];
        g_part[kind * 32 + ch][pidx] = v;
    }
}

// ===== k_pre: inproj (18->32) + conv layer-0 + partials =====
__global__ __launch_bounds__(NTH, 4) void k_pre(const float* __restrict__ x,
                                                const float* __restrict__ in_w,
                                                const float* __restrict__ in_b,
                                                const float* __restrict__ cw0) {
    __shared__ __align__(16) float xs[68 * 19];    // also conv red area (needs 576)
    __shared__ __align__(16) float yb[68 * 36];
    __shared__ __align__(16) float wsin[576];
    __shared__ __align__(16) float bsin[32];
    __shared__ __align__(16) float cw[3072];
    int tid = threadIdx.x;
    int fb = blockIdx.x * T_CORE;
    int E = min(T_CORE, F_N - fb);
    size_t rowbase = (size_t)blockIdx.y * F_N;

    for (int idx = tid; idx < (E + 2) * 18; idx += NTH) {
        int s = idx / 18, i = idx - s * 18;
        int f = fb - 1 + s;
        xs[s * 19 + i] = (f >= 0 && f < F_N) ? x[(rowbase + f) * 18 + i] : 0.f;
    }
    for (int idx = tid; idx < 576; idx += NTH) wsin[idx] = in_w[idx];
    if (tid < 32) bsin[tid] = in_b[tid];
    for (int idx = tid; idx < 3072; idx += NTH) cw[idx] = cw0[idx];
    __syncthreads();

    int s = tid;
    if (s < E + 2) {
        int f = fb - 1 + s;
        u64 acc[16];
        if (f >= 0 && f < F_N) {
            const u64* b2 = (const u64*)bsin;
#pragma unroll
            for (int k = 0; k < 16; k++) acc[k] = b2[k];
#pragma unroll
            for (int i = 0; i < 18; i++) {
                u64 a2 = pack2(xs[s * 19 + i]);
                const u64* wr = (const u64*)(wsin + i * 32);
#pragma unroll
                for (int k = 0; k < 16; k++) ffma2(acc[k], a2, wr[k]);
            }
        } else {
#pragma unroll
            for (int k = 0; k < 16; k++) acc[k] = 0ull;
        }
        ulonglong2* o = (ulonglong2*)&yb[s * 36];
#pragma unroll
        for (int k = 0; k < 8; k++) o[k] = make_ulonglong2(acc[2 * k], acc[2 * k + 1]);
    }
    __syncthreads();

    for (int idx = tid; idx < E * 32; idx += NTH) {
        int t = idx >> 5, c = idx & 31;
        g_h[0][(rowbase + fb + t) * 32 + c] = yb[(t + 1) * 36 + c];
    }
    conv_phase(yb, cw, fb, E, rowbase, (int)blockIdx.y * NBX + blockIdx.x, xs, g_c[0]);
}

// ===== BN finalize: one block per channel, coalesced + vectorized =====
__global__ __launch_bounds__(256) void k_bnfin(const float* __restrict__ bng,
                                               const float* __restrict__ bnb) {
    __shared__ float rs[256], rq[256];
    int c = blockIdx.x;
    float s = 0.f, q = 0.f;
    const float4* pr = (const float4*)g_part[c];
    const float4* qr = (const float4*)g_part[32 + c];
    for (int i = threadIdx.x; i < NPART / 4; i += 256) {
        float4 a = pr[i]; s += a.x + a.y + a.z + a.w;
        float4 b = qr[i]; q += b.x + b.y + b.z + b.w;
    }
    rs[threadIdx.x] = s; rq[threadIdx.x] = q;
    __syncthreads();
    for (int off = 128; off > 0; off >>= 1) {
        if (threadIdx.x < off) {
            rs[threadIdx.x] += rs[threadIdx.x + off];
            rq[threadIdx.x] += rq[threadIdx.x + off];
        }
        __syncthreads();
    }
    if (threadIdx.x == 0) {
        float mean = rs[0] * (1.0f / BF_N);
        float var = rq[0] * (1.0f / BF_N) - mean * mean;
        float a = rsqrtf(var + 1e-5f) * bng[c];
        g_bn[0][c] = a;
        g_bn[1][c] = bnb[c] - mean * a;
    }
}

// ===== fused layer: qkv GEMM + banded attn + proj + BN/GELU + LN(+write) + next-conv =====
// smem floats:
//   R1 [0,2304):        ht [32][72] channel-major -> as_ [67][34] (2278) after B -> conv red
//   qs [2304,9504):     stage temp [72][33] -> [72][100] q|k|v -> y [67][36] + cw (at +2412)
//   wq [9504,12576)     32x96
//   wp [12576,13600)    32x32
//   params [13600,13760)
#define SMEM_APPLY (13760 * 4)
__global__ __launch_bounds__(NTH, 4) void k_apply(const float* __restrict__ qw,
                                                  const float* __restrict__ pw,
                                                  const float* __restrict__ pbias,
                                                  const float* __restrict__ lng,
                                                  const float* __restrict__ lnb,
                                                  const float* __restrict__ cwn,
                                                  int src, int cidx, int last) {
    extern __shared__ float sm[];
    float* R1 = sm;               // ht then as_
    float* qs = sm + 2304;        // temp, then qkv, later y + cw
    float* wq = sm + 9504;
    float* wp = sm + 12576;
    float* pb = sm + 13600;
    float* lg = pb + 32;
    float* lb = lg + 32;
    float* bna = lb + 32;
    float* bnb = bna + 32;

    float* ht = R1;               // [32][72]
    float* as_ = R1;              // [67][34] (after B; ht dead); 8B-aligned rows
    float* y = qs;                // [67][36] (after C; qs rows dead)
    float* cw = qs + 2412;        // 3072 floats

    int tid = threadIdx.x;
    int fb = blockIdx.x * T_CORE;
    int E = min(T_CORE, F_N - fb);
    size_t rowbase = (size_t)blockIdx.y * F_N;
    const float* hsrc = g_h[src];
    float* hdst = g_h[src ^ 1];
    const float* gc_in = g_c[cidx];
    float* gc_out = g_c[cidx ^ 1];

    // ---- stage 1: coalesced LDG token-major into temp [72][33] (in qs region) ----
    float* tmp = qs;
    for (int idx = tid; idx < 72 * 32; idx += NTH) {
        int t = idx >> 5, c = idx & 31;
        int f = fb - 1 + t;
        tmp[t * 33 + c] = (f >= 0 && f < F_N) ? hsrc[(rowbase + f) * 32 + c] : 0.f;
    }
    for (int idx = tid; idx < 3072; idx += NTH) wq[idx] = qw[idx];
    for (int idx = tid; idx < 1024; idx += NTH) wp[idx] = pw[idx];
    if (tid < 32) {
        pb[tid] = pbias[tid]; lg[tid] = lng[tid]; lb[tid] = lnb[tid];
        bna[tid] = g_bn[0][tid]; bnb[tid] = g_bn[1][tid];
    }
    __syncthreads();

    // ---- stage 2: conflict-free smem transpose -> ht [32][72] channel-major ----
    for (int idx = tid; idx < 32 * 72; idx += NTH) {
        int c = idx / 72, t = idx - c * 72;
        ht[c * 72 + t] = tmp[t * 33 + c];
    }
    __syncthreads();

    // ---- Phase B: qkv GEMM (72 tok x 96 ch, K=32), 4 tok x 8 ch, FFMA2; 216 units ----
    if (tid < 216) {
        int og = tid / 18, tg = tid - og * 18;
        int t0 = tg * 4, oc = og * 8;
        u64 acc2[4][4];
#pragma unroll
        for (int a = 0; a < 4; a++)
#pragma unroll
            for (int k = 0; k < 4; k++) acc2[a][k] = 0ull;
#pragma unroll
        for (int i = 0; i < 32; i++) {
            float4 av = *reinterpret_cast<const float4*>(&ht[i * 72 + t0]);
            const u64* wr = reinterpret_cast<const u64*>(&wq[i * 96 + oc]);
            u64 w0 = wr[0], w1 = wr[1], w2 = wr[2], w3 = wr[3];
            u64 a0 = pack2(av.x), a1 = pack2(av.y), a2 = pack2(av.z), a3 = pack2(av.w);
            ffma2(acc2[0][0], a0, w0); ffma2(acc2[0][1], a0, w1); ffma2(acc2[0][2], a0, w2); ffma2(acc2[0][3], a0, w3);
            ffma2(acc2[1][0], a1, w0); ffma2(acc2[1][1], a1, w1); ffma2(acc2[1][2], a1, w2); ffma2(acc2[1][3], a1, w3);
            ffma2(acc2[2][0], a2, w0); ffma2(acc2[2][1], a2, w1); ffma2(acc2[2][2], a2, w2); ffma2(acc2[2][3], a2, w3);
            ffma2(acc2[3][0], a3, w0); ffma2(acc2[3][1], a3, w1); ffma2(acc2[3][2], a3, w2); ffma2(acc2[3][3], a3, w3);
        }
#pragma unroll
        for (int a = 0; a < 4; a++) {
            ulonglong2* dst = reinterpret_cast<ulonglong2*>(&qs[(t0 + a) * 100 + oc]);
            dst[0] = make_ulonglong2(acc2[a][0], acc2[a][1]);
            dst[1] = make_ulonglong2(acc2[a][2], acc2[a][3]);
        }
    }
    __syncthreads();

    // ---- Phase C: banded attention, warp per slot (lane=channel) -> as_ (over dead ht) ----
    int warp = tid >> 5, lane = tid & 31;
    for (int rep = 0; rep < 8; rep++) {
        int s = rep * 9 + warp;
        if (s >= 67) break;
        int f = fb - 1 + s;
        if (f >= 0 && f < F_N) {
            float qv = qs[s * 100 + lane];
            float sc[3];
#pragma unroll
            for (int j = 0; j < 3; j++) {
                float p = qv * qs[(s + j) * 100 + 32 + lane];
                p += __shfl_xor_sync(0xffffffffu, p, 1);
                p += __shfl_xor_sync(0xffffffffu, p, 2);
                p += __shfl_xor_sync(0xffffffffu, p, 4);
                sc[j] = (f + j < F_N) ? p * 0.35355339059327373f : -INFINITY;
            }
            float m = fmaxf(sc[0], fmaxf(sc[1], sc[2]));
            float e0 = __expf(sc[0] - m);
            float e1 = (f + 1 < F_N) ? __expf(sc[1] - m) : 0.f;
            float e2 = (f + 2 < F_N) ? __expf(sc[2] - m) : 0.f;
            float inv = 1.f / (e0 + e1 + e2);
            float ao = (e0 * qs[s * 100 + 64 + lane]
                      + e1 * qs[(s + 1) * 100 + 64 + lane]
                      + e2 * qs[(s + 2) * 100 + 64 + lane]) * inv;
            as_[s * 34 + lane] = ao;
        } else {
            as_[s * 34 + lane] = 0.f;
        }
    }
    __syncthreads();

    // qs rows dead: overlay next-layer conv weights (disjoint from y region)
    if (!last)
        for (int idx = tid; idx < 3072; idx += NTH) cw[idx] = cwn[idx];

    // ---- Phase D: proj + BN(c)/GELU + residual + LayerNorm + global write -> y (ONE pass) ----
    {
        int sl = tid;
        bool valid = sl < 268;
        int s = valid ? (sl >> 2) : 0;
        int o0 = (sl & 3) << 3;
        int f = fb - 1 + s;
        bool fv = valid && f >= 0 && f < F_N;
        float yv[8];
        if (fv) {
            u64 acc2[4];
            const u64* pb2 = (const u64*)(pb + o0);
            acc2[0] = pb2[0]; acc2[1] = pb2[1]; acc2[2] = pb2[2]; acc2[3] = pb2[3];
            const u64* ar = (const u64*)(as_ + s * 34);   // 8B-aligned (s*136 bytes)
#pragma unroll
            for (int i2 = 0; i2 < 16; i2++) {
                float2 aa = unpack2(ar[i2]);
                u64 a0 = pack2(aa.x), a1 = pack2(aa.y);
                const u64* w0 = (const u64*)(wp + (2 * i2) * 32 + o0);
                const u64* w1 = (const u64*)(wp + (2 * i2 + 1) * 32 + o0);
                ffma2(acc2[0], a0, w0[0]); ffma2(acc2[1], a0, w0[1]);
                ffma2(acc2[2], a0, w0[2]); ffma2(acc2[3], a0, w0[3]);
                ffma2(acc2[0], a1, w1[0]); ffma2(acc2[1], a1, w1[1]);
                ffma2(acc2[2], a1, w1[2]); ffma2(acc2[3], a1, w1[3]);
            }
            const float4* cg = (const float4*)&gc_in[(rowbase + f) * 32 + o0];
            float4 c0 = cg[0], c1 = cg[1];
            float cv[8] = {c0.x, c0.y, c0.z, c0.w, c1.x, c1.y, c1.z, c1.w};
#pragma unroll
            for (int k = 0; k < 4; k++) {
                float2 pa = unpack2(acc2[k]);
                float cn0 = cv[2 * k] * bna[o0 + 2 * k] + bnb[o0 + 2 * k];
                float cn1 = cv[2 * k + 1] * bna[o0 + 2 * k + 1] + bnb[o0 + 2 * k + 1];
                yv[2 * k] = gelu_f(cn0) + pa.x;
                yv[2 * k + 1] = gelu_f(cn1) + pa.y;
            }
        } else {
#pragma unroll
            for (int j = 0; j < 8; j++) yv[j] = 0.f;
        }
        // LayerNorm across the 4 threads of this token (uniform shfl execution)
        float ls = 0.f, lq = 0.f;
#pragma unroll
        for (int j = 0; j < 8; j++) { ls += yv[j]; lq += yv[j] * yv[j]; }
        ls += __shfl_xor_sync(0xffffffffu, ls, 1);
        ls += __shfl_xor_sync(0xffffffffu, ls, 2);
        lq += __shfl_xor_sync(0xffffffffu, lq, 1);
        lq += __shfl_xor_sync(0xffffffffu, lq, 2);
        float mean = ls * (1.f / 32.f);
        float var = lq * (1.f / 32.f) - mean * mean;
        float rstd = rsqrtf(var + 1e-5f);
        float ov[8];
#pragma unroll
        for (int j = 0; j < 8; j++)
            ov[j] = (yv[j] - mean) * rstd * lg[o0 + j] + lb[o0 + j];
        if (fv) {
            float4* yo = (float4*)&y[s * 36 + o0];
            yo[0] = make_float4(ov[0], ov[1], ov[2], ov[3]);
            yo[1] = make_float4(ov[4], ov[5], ov[6], ov[7]);
            if (s >= 1 && s <= E) {
                float4* ho = (float4*)&hdst[(rowbase + f) * 32 + o0];
                ho[0] = make_float4(ov[0], ov[1], ov[2], ov[3]);
                ho[1] = make_float4(ov[4], ov[5], ov[6], ov[7]);
            }
        }
    }
    if (last) return;
    __syncthreads();

    // ---- fused next-layer conv on smem y ----
    conv_phase(y, cw, fb, E, rowbase, (int)blockIdx.y * NBX + blockIdx.x, R1, gc_out);
}

// ===== head: gelu(h@W1+b1) @ W2 + b2 -> sigmoid =====
__global__ __launch_bounds__(256) void k_head(const float* __restrict__ w1,
                                              const float* __restrict__ b1,
                                              const float* __restrict__ w2,
                                              const float* __restrict__ b2,
                                              float* __restrict__ out) {
    __shared__ __align__(16) float hsm[256][33];
    __shared__ __align__(16) float ws1[512];
    __shared__ __align__(16) float wb1[16];
    __shared__ __align__(16) float ws2[16];
    __shared__ float b2s;
    int t0 = blockIdx.x * 256;
    const float* hsrc = g_h[0];
    for (int idx = threadIdx.x; idx < 256 * 32; idx += 256) {
        int tok = idx >> 5, c = idx & 31;
        hsm[tok][c] = hsrc[(size_t)(t0 + tok) * 32 + c];
    }
    for (int idx = threadIdx.x; idx < 512; idx += 256) ws1[idx] = w1[idx];
    if (threadIdx.x < 16) { wb1[threadIdx.x] = b1[threadIdx.x]; ws2[threadIdx.x] = w2[threadIdx.x]; }
    if (threadIdx.x == 0) b2s = b2[0];
    __syncthreads();

    const float* hr = hsm[threadIdx.x];
    u64 s2[8];
    const u64* wb2 = (const u64*)wb1;
#pragma unroll
    for (int k = 0; k < 8; k++) s2[k] = wb2[k];
#pragma unroll
    for (int i = 0; i < 32; i++) {
        u64 a2 = pack2(hr[i]);
        const u64* wr = (const u64*)(ws1 + i * 16);
#pragma unroll
        for (int k = 0; k < 8; k++) ffma2(s2[k], a2, wr[k]);
    }
    float m = b2s;
#pragma unroll
    for (int k = 0; k < 8; k++) {
        float2 f2 = unpack2(s2[k]);
        m += gelu_f(f2.x) * ws2[2 * k] + gelu_f(f2.y) * ws2[2 * k + 1];
    }
    out[t0 + threadIdx.x] = 1.f / (1.f + expf(-m));
}

// ===== launcher =====
extern "C" void kernel_launch(void* const* d_in, const int* in_sizes, int n_in,
                              void* d_out, int out_size) {
    const float* x      = (const float*)d_in[0];
    const float* in_w   = (const float*)d_in[1];
    const float* in_b   = (const float*)d_in[2];
    const float* conv_w = (const float*)d_in[3];
    const float* bn_g   = (const float*)d_in[4];
    const float* bn_b   = (const float*)d_in[5];
    const float* qkv_w  = (const float*)d_in[6];
    const float* proj_w = (const float*)d_in[7];
    const float* proj_b = (const float*)d_in[8];
    const float* ln_g   = (const float*)d_in[9];
    const float* ln_b   = (const float*)d_in[10];
    const float* h1_w   = (const float*)d_in[11];
    const float* h1_b   = (const float*)d_in[12];
    const float* h2_w   = (const float*)d_in[13];
    const float* h2_b   = (const float*)d_in[14];
    float* out = (float*)d_out;

    cudaFuncSetAttribute(k_apply, cudaFuncAttributeMaxDynamicSharedMemorySize, SMEM_APPLY);

    dim3 grid(NBX, B_N);
    k_pre<<<grid, NTH>>>(x, in_w, in_b, conv_w);
    for (int l = 0; l < 4; l++) {
        int src = l & 1;
        int cidx = l & 1;   // layer l reads g_c[l&1], writes g_c[(l&1)^1]
        int last = (l == 3) ? 1 : 0;
        k_bnfin<<<32, 256>>>(bn_g + l * 32, bn_b + l * 32);
        k_apply<<<grid, NTH, SMEM_APPLY>>>(qkv_w + l * 3072, proj_w + l * 1024,
                                           proj_b + l * 32, ln_g + l * 32, ln_b + l * 32,
                                           conv_w + (l + 1 < 4 ? l + 1 : 0) * 3072,
                                           src, cidx, last);
    }
    k_head<<<BF_N / 256, 256>>>(h1_w, h1_b, h2_w, h2_b, out);
}

// round 12
// speedup vs baseline: 2.5457x; 1.1094x over previous
#include <cuda_runtime.h>
#include <math.h>

#define B_N 1024
#define F_N 257
#define BF_N (B_N * F_N)
#define T_CORE 65
#define NBX 4
#define NPART (NBX * B_N)   // 4096
#define NTH 288             // 9 warps

typedef unsigned long long u64;

// -------- device scratch (allocation-free) --------
__device__ __align__(16) float g_h[2][(size_t)BF_N * 32];
__device__ __align__(16) float g_c[2][(size_t)BF_N * 32];   // ping-pong per layer
__device__ __align__(16) float g_part[64][NPART];           // [kind*32+ch][block]
__device__ __align__(16) float g_bn[2][32];

__device__ __forceinline__ float gelu_f(float x) {
    return 0.5f * x * (1.0f + erff(x * 0.70710678118654752440f));
}
__device__ __forceinline__ void ffma2(u64& d, u64 a, u64 b) {
    asm("fma.rn.f32x2 %0, %1, %2, %0;" : "+l"(d) : "l"(a), "l"(b));
}
__device__ __forceinline__ u64 pack2(float x) {
    u64 r; asm("mov.b64 %0, {%1, %1};" : "=l"(r) : "f"(x)); return r;
}
__device__ __forceinline__ float2 unpack2(u64 a) {
    float2 f; asm("mov.b64 {%0, %1}, %2;" : "=f"(f.x), "=f"(f.y) : "l"(a)); return f;
}

// ===== conv (width-3 over F) on smem y + BN partials; ALL NTH threads call =====
// Token-PAIR per thread: weights read once per pair; invalid-f y rows are ZERO
// (written by Phase D / inproj), so SAME padding needs no tap masks.
// Rows read: sA-1 .. sA+2 (row 67 may be garbage but only feeds a discarded accB).
__device__ __forceinline__ void conv_phase(const float* y, const float* cws,
                                           int fb, int E, size_t rowbase,
                                           int pidx, float* red, float* gc_out) {
    int tid = threadIdx.x;
    int pr = tid >> 2, o0 = (tid & 3) << 3;
    int tA = pr * 2;
    float s1[8], s2[8];
#pragma unroll
    for (int j = 0; j < 8; j++) { s1[j] = 0.f; s2[j] = 0.f; }
    if (tA < E) {
        bool vB = (tA + 1) < E;
        int sA = tA + 1;
        u64 accA[4] = {0ull, 0ull, 0ull, 0ull};
        u64 accB[4] = {0ull, 0ull, 0ull, 0ull};
#pragma unroll
        for (int i4 = 0; i4 < 8; i4++) {
            float4 rr[4];
#pragma unroll
            for (int r = 0; r < 4; r++)
                rr[r] = ((const float4*)(y + (sA - 1 + r) * 36))[i4];
#pragma unroll
            for (int w = 0; w < 3; w++) {
                const float* wb = cws + w * 1024 + (i4 * 4) * 32 + o0;
                float4 va = rr[w], vb = rr[w + 1];
                u64 a0 = pack2(va.x), a1 = pack2(va.y), a2 = pack2(va.z), a3 = pack2(va.w);
                u64 b0 = pack2(vb.x), b1 = pack2(vb.y), b2 = pack2(vb.z), b3 = pack2(vb.w);
#define CSTEP(AK, BK, ROW) \
                { const u64* wk = (const u64*)(wb + (ROW) * 32); \
                  u64 q0 = wk[0], q1 = wk[1], q2 = wk[2], q3 = wk[3]; \
                  ffma2(accA[0], AK, q0); ffma2(accA[1], AK, q1); \
                  ffma2(accA[2], AK, q2); ffma2(accA[3], AK, q3); \
                  ffma2(accB[0], BK, q0); ffma2(accB[1], BK, q1); \
                  ffma2(accB[2], BK, q2); ffma2(accB[3], BK, q3); }
                CSTEP(a0, b0, 0)
                CSTEP(a1, b1, 1)
                CSTEP(a2, b2, 2)
                CSTEP(a3, b3, 3)
#undef CSTEP
            }
        }
        int fA = fb + tA;
        ulonglong2* co = (ulonglong2*)&gc_out[(rowbase + fA) * 32 + o0];
        co[0] = make_ulonglong2(accA[0], accA[1]);
        co[1] = make_ulonglong2(accA[2], accA[3]);
#pragma unroll
        for (int k = 0; k < 4; k++) {
            float2 f2 = unpack2(accA[k]);
            s1[2 * k] += f2.x;     s2[2 * k] += f2.x * f2.x;
            s1[2 * k + 1] += f2.y; s2[2 * k + 1] += f2.y * f2.y;
        }
        if (vB) {
            ulonglong2* cb = (ulonglong2*)&gc_out[(rowbase + fA + 1) * 32 + o0];
            cb[0] = make_ulonglong2(accB[0], accB[1]);
            cb[1] = make_ulonglong2(accB[2], accB[3]);
#pragma unroll
            for (int k = 0; k < 4; k++) {
                float2 f2 = unpack2(accB[k]);
                s1[2 * k] += f2.x;     s2[2 * k] += f2.x * f2.x;
                s1[2 * k + 1] += f2.y; s2[2 * k + 1] += f2.y * f2.y;
            }
        }
    }
#pragma unroll
    for (int off = 4; off < 32; off <<= 1) {
#pragma unroll
        for (int j = 0; j < 8; j++) {
            s1[j] += __shfl_xor_sync(0xffffffffu, s1[j], off);
            s2[j] += __shfl_xor_sync(0xffffffffu, s2[j], off);
        }
    }
    int warp = tid >> 5, lane = tid & 31;
    if (lane < 4) {
#pragma unroll
        for (int j = 0; j < 8; j++) {
            red[((warp * 4 + lane) * 8 + j) * 2 + 0] = s1[j];
            red[((warp * 4 + lane) * 8 + j) * 2 + 1] = s2[j];
        }
    }
    __syncthreads();
    if (tid < 64) {
        int kind = tid >> 5, ch = tid & 31;
        int sl = ch >> 3, j = ch & 7;
        float v = 0.f;
#pragma unroll
        for (int w2 = 0; w2 < 9; w2++) v += red[((w2 * 4 + sl) * 8 + j) * 2 + kind];
        g_part[kind * 32 + ch][pidx] = v;
    }
}

// ===== k_pre: inproj (18->32) + conv layer-0 + partials =====
__global__ __launch_bounds__(NTH, 3) void k_pre(const float* __restrict__ x,
                                                const float* __restrict__ in_w,
                                                const float* __restrict__ in_b,
                                                const float* __restrict__ cw0) {
    __shared__ __align__(16) float xs[68 * 19];    // also conv red area (needs 576)
    __shared__ __align__(16) float yb[68 * 36];
    __shared__ __align__(16) float wsin[576];
    __shared__ __align__(16) float bsin[32];
    __shared__ __align__(16) float cw[3072];
    int tid = threadIdx.x;
    int fb = blockIdx.x * T_CORE;
    int E = min(T_CORE, F_N - fb);
    size_t rowbase = (size_t)blockIdx.y * F_N;

    for (int idx = tid; idx < (E + 2) * 18; idx += NTH) {
        int s = idx / 18, i = idx - s * 18;
        int f = fb - 1 + s;
        xs[s * 19 + i] = (f >= 0 && f < F_N) ? x[(rowbase + f) * 18 + i] : 0.f;
    }
    for (int idx = tid; idx < 576; idx += NTH) wsin[idx] = in_w[idx];
    if (tid < 32) bsin[tid] = in_b[tid];
    for (int idx = tid; idx < 3072; idx += NTH) cw[idx] = cw0[idx];
    __syncthreads();

    int s = tid;
    if (s < E + 2) {
        int f = fb - 1 + s;
        u64 acc[16];
        if (f >= 0 && f < F_N) {
            const u64* b2 = (const u64*)bsin;
#pragma unroll
            for (int k = 0; k < 16; k++) acc[k] = b2[k];
#pragma unroll
            for (int i = 0; i < 18; i++) {
                u64 a2 = pack2(xs[s * 19 + i]);
                const u64* wr = (const u64*)(wsin + i * 32);
#pragma unroll
                for (int k = 0; k < 16; k++) ffma2(acc[k], a2, wr[k]);
            }
        } else {
#pragma unroll
            for (int k = 0; k < 16; k++) acc[k] = 0ull;
        }
        ulonglong2* o = (ulonglong2*)&yb[s * 36];
#pragma unroll
        for (int k = 0; k < 8; k++) o[k] = make_ulonglong2(acc[2 * k], acc[2 * k + 1]);
    }
    __syncthreads();

    for (int idx = tid; idx < E * 32; idx += NTH) {
        int t = idx >> 5, c = idx & 31;
        g_h[0][(rowbase + fb + t) * 32 + c] = yb[(t + 1) * 36 + c];
    }
    conv_phase(yb, cw, fb, E, rowbase, (int)blockIdx.y * NBX + blockIdx.x, xs, g_c[0]);
}

// ===== BN finalize: one block per channel, coalesced + vectorized =====
__global__ __launch_bounds__(256) void k_bnfin(const float* __restrict__ bng,
                                               const float* __restrict__ bnb) {
    __shared__ float rs[256], rq[256];
    int c = blockIdx.x;
    float s = 0.f, q = 0.f;
    const float4* pr = (const float4*)g_part[c];
    const float4* qr = (const float4*)g_part[32 + c];
    for (int i = threadIdx.x; i < NPART / 4; i += 256) {
        float4 a = pr[i]; s += a.x + a.y + a.z + a.w;
        float4 b = qr[i]; q += b.x + b.y + b.z + b.w;
    }
    rs[threadIdx.x] = s; rq[threadIdx.x] = q;
    __syncthreads();
    for (int off = 128; off > 0; off >>= 1) {
        if (threadIdx.x < off) {
            rs[threadIdx.x] += rs[threadIdx.x + off];
            rq[threadIdx.x] += rq[threadIdx.x + off];
        }
        __syncthreads();
    }
    if (threadIdx.x == 0) {
        float mean = rs[0] * (1.0f / BF_N);
        float var = rq[0] * (1.0f / BF_N) - mean * mean;
        float a = rsqrtf(var + 1e-5f) * bng[c];
        g_bn[0][c] = a;
        g_bn[1][c] = bnb[c] - mean * a;
    }
}

// ===== fused layer: qkv GEMM + banded attn + proj + BN/GELU + LN(+write) + next-conv =====
// smem floats:
//   R1 [0,2304):        ht [32][72] channel-major -> as_ [67][34] (2278) after B -> conv red
//   qs [2304,9504):     stage temp [72][33] -> [72][100] q|k|v -> y [67][36] + cw (at +2412)
//   wq [9504,12576)     32x96
//   wp [12576,13600)    32x32
//   params [13600,13760)
#define SMEM_APPLY (13760 * 4)
__global__ __launch_bounds__(NTH, 3) void k_apply(const float* __restrict__ qw,
                                                  const float* __restrict__ pw,
                                                  const float* __restrict__ pbias,
                                                  const float* __restrict__ lng,
                                                  const float* __restrict__ lnb,
                                                  const float* __restrict__ cwn,
                                                  int src, int cidx, int last) {
    extern __shared__ float sm[];
    float* R1 = sm;               // ht then as_
    float* qs = sm + 2304;        // temp, then qkv, later y + cw
    float* wq = sm + 9504;
    float* wp = sm + 12576;
    float* pb = sm + 13600;
    float* lg = pb + 32;
    float* lb = lg + 32;
    float* bna = lb + 32;
    float* bnb = bna + 32;

    float* ht = R1;               // [32][72]
    float* as_ = R1;              // [67][34] (after B; ht dead); 8B-aligned rows
    float* y = qs;                // [67][36] (after C; qs rows dead)
    float* cw = qs + 2412;        // 3072 floats

    int tid = threadIdx.x;
    int fb = blockIdx.x * T_CORE;
    int E = min(T_CORE, F_N - fb);
    size_t rowbase = (size_t)blockIdx.y * F_N;
    const float* hsrc = g_h[src];
    float* hdst = g_h[src ^ 1];
    const float* gc_in = g_c[cidx];
    float* gc_out = g_c[cidx ^ 1];

    // ---- stage 1: coalesced LDG token-major into temp [72][33] (in qs region) ----
    float* tmp = qs;
    for (int idx = tid; idx < 72 * 32; idx += NTH) {
        int t = idx >> 5, c = idx & 31;
        int f = fb - 1 + t;
        tmp[t * 33 + c] = (f >= 0 && f < F_N) ? hsrc[(rowbase + f) * 32 + c] : 0.f;
    }
    for (int idx = tid; idx < 3072; idx += NTH) wq[idx] = qw[idx];
    for (int idx = tid; idx < 1024; idx += NTH) wp[idx] = pw[idx];
    if (tid < 32) {
        pb[tid] = pbias[tid]; lg[tid] = lng[tid]; lb[tid] = lnb[tid];
        bna[tid] = g_bn[0][tid]; bnb[tid] = g_bn[1][tid];
    }
    __syncthreads();

    // ---- stage 2: conflict-free smem transpose -> ht [32][72] channel-major ----
    for (int idx = tid; idx < 32 * 72; idx += NTH) {
        int c = idx / 72, t = idx - c * 72;
        ht[c * 72 + t] = tmp[t * 33 + c];
    }
    __syncthreads();

    // ---- Phase B: qkv GEMM (72 tok x 96 ch, K=32), 4 tok x 8 ch, FFMA2; 216 units ----
    if (tid < 216) {
        int og = tid / 18, tg = tid - og * 18;
        int t0 = tg * 4, oc = og * 8;
        u64 acc2[4][4];
#pragma unroll
        for (int a = 0; a < 4; a++)
#pragma unroll
            for (int k = 0; k < 4; k++) acc2[a][k] = 0ull;
#pragma unroll
        for (int i = 0; i < 32; i++) {
            float4 av = *reinterpret_cast<const float4*>(&ht[i * 72 + t0]);
            const u64* wr = reinterpret_cast<const u64*>(&wq[i * 96 + oc]);
            u64 w0 = wr[0], w1 = wr[1], w2 = wr[2], w3 = wr[3];
            u64 a0 = pack2(av.x), a1 = pack2(av.y), a2 = pack2(av.z), a3 = pack2(av.w);
            ffma2(acc2[0][0], a0, w0); ffma2(acc2[0][1], a0, w1); ffma2(acc2[0][2], a0, w2); ffma2(acc2[0][3], a0, w3);
            ffma2(acc2[1][0], a1, w0); ffma2(acc2[1][1], a1, w1); ffma2(acc2[1][2], a1, w2); ffma2(acc2[1][3], a1, w3);
            ffma2(acc2[2][0], a2, w0); ffma2(acc2[2][1], a2, w1); ffma2(acc2[2][2], a2, w2); ffma2(acc2[2][3], a2, w3);
            ffma2(acc2[3][0], a3, w0); ffma2(acc2[3][1], a3, w1); ffma2(acc2[3][2], a3, w2); ffma2(acc2[3][3], a3, w3);
        }
#pragma unroll
        for (int a = 0; a < 4; a++) {
            ulonglong2* dst = reinterpret_cast<ulonglong2*>(&qs[(t0 + a) * 100 + oc]);
            dst[0] = make_ulonglong2(acc2[a][0], acc2[a][1]);
            dst[1] = make_ulonglong2(acc2[a][2], acc2[a][3]);
        }
    }
    __syncthreads();

    // ---- Phase C: banded attention, warp per slot (lane=channel) -> as_ (over dead ht) ----
    int warp = tid >> 5, lane = tid & 31;
    for (int rep = 0; rep < 8; rep++) {
        int s = rep * 9 + warp;
        if (s >= 67) break;
        int f = fb - 1 + s;
        if (f >= 0 && f < F_N) {
            float qv = qs[s * 100 + lane];
            float sc[3];
#pragma unroll
            for (int j = 0; j < 3; j++) {
                float p = qv * qs[(s + j) * 100 + 32 + lane];
                p += __shfl_xor_sync(0xffffffffu, p, 1);
                p += __shfl_xor_sync(0xffffffffu, p, 2);
                p += __shfl_xor_sync(0xffffffffu, p, 4);
                sc[j] = (f + j < F_N) ? p * 0.35355339059327373f : -INFINITY;
            }
            float m = fmaxf(sc[0], fmaxf(sc[1], sc[2]));
            float e0 = __expf(sc[0] - m);
            float e1 = (f + 1 < F_N) ? __expf(sc[1] - m) : 0.f;
            float e2 = (f + 2 < F_N) ? __expf(sc[2] - m) : 0.f;
            float inv = 1.f / (e0 + e1 + e2);
            float ao = (e0 * qs[s * 100 + 64 + lane]
                      + e1 * qs[(s + 1) * 100 + 64 + lane]
                      + e2 * qs[(s + 2) * 100 + 64 + lane]) * inv;
            as_[s * 34 + lane] = ao;
        } else {
            as_[s * 34 + lane] = 0.f;
        }
    }
    __syncthreads();

    // qs rows dead: overlay next-layer conv weights (disjoint from y region)
    if (!last)
        for (int idx = tid; idx < 3072; idx += NTH) cw[idx] = cwn[idx];

    // ---- Phase D: proj + BN(c)/GELU + residual + LN + writes; TOKEN-PAIR per thread ----
    {
        int p2 = tid >> 2;
        int o0 = (tid & 3) << 3;
        int sA = p2 * 2, sB = sA + 1;
        bool vp = p2 < 34;
        int fA_ = fb - 1 + sA;
        int fB_ = fA_ + 1;
        bool fvA = vp && (fA_ >= 0) && (fA_ < F_N);
        bool fvB = vp && (sB < 67) && (fB_ >= 0) && (fB_ < F_N);
        float yvA[8], yvB[8];
#pragma unroll
        for (int j = 0; j < 8; j++) { yvA[j] = 0.f; yvB[j] = 0.f; }
        if (vp) {
            u64 accA[4], accB[4];
            const u64* pb2 = (const u64*)(pb + o0);
#pragma unroll
            for (int k = 0; k < 4; k++) { accA[k] = pb2[k]; accB[k] = pb2[k]; }
            const u64* arA = (const u64*)(as_ + sA * 34);
            const u64* arB = (const u64*)(as_ + sB * 34);
#pragma unroll
            for (int i2 = 0; i2 < 16; i2++) {
                float2 fa = unpack2(arA[i2]);
                float2 fbv = unpack2(arB[i2]);
                u64 a0 = pack2(fa.x), a1 = pack2(fa.y);
                u64 b0 = pack2(fbv.x), b1 = pack2(fbv.y);
                const u64* w0 = (const u64*)(wp + (2 * i2) * 32 + o0);
                const u64* w1 = (const u64*)(wp + (2 * i2 + 1) * 32 + o0);
                u64 q0 = w0[0], q1 = w0[1], q2 = w0[2], q3 = w0[3];
                u64 r0 = w1[0], r1 = w1[1], r2 = w1[2], r3 = w1[3];
                ffma2(accA[0], a0, q0); ffma2(accA[1], a0, q1); ffma2(accA[2], a0, q2); ffma2(accA[3], a0, q3);
                ffma2(accA[0], a1, r0); ffma2(accA[1], a1, r1); ffma2(accA[2], a1, r2); ffma2(accA[3], a1, r3);
                ffma2(accB[0], b0, q0); ffma2(accB[1], b0, q1); ffma2(accB[2], b0, q2); ffma2(accB[3], b0, q3);
                ffma2(accB[0], b1, r0); ffma2(accB[1], b1, r1); ffma2(accB[2], b1, r2); ffma2(accB[3], b1, r3);
            }
            if (fvA) {
                const float4* cg = (const float4*)&gc_in[(rowbase + fA_) * 32 + o0];
                float4 c0 = cg[0], c1 = cg[1];
                float cv[8] = {c0.x, c0.y, c0.z, c0.w, c1.x, c1.y, c1.z, c1.w};
#pragma unroll
                for (int k = 0; k < 4; k++) {
                    float2 pa = unpack2(accA[k]);
                    float cn0 = cv[2 * k] * bna[o0 + 2 * k] + bnb[o0 + 2 * k];
                    float cn1 = cv[2 * k + 1] * bna[o0 + 2 * k + 1] + bnb[o0 + 2 * k + 1];
                    yvA[2 * k] = gelu_f(cn0) + pa.x;
                    yvA[2 * k + 1] = gelu_f(cn1) + pa.y;
                }
            }
            if (fvB) {
                const float4* cg = (const float4*)&gc_in[(rowbase + fB_) * 32 + o0];
                float4 c0 = cg[0], c1 = cg[1];
                float cv[8] = {c0.x, c0.y, c0.z, c0.w, c1.x, c1.y, c1.z, c1.w};
#pragma unroll
                for (int k = 0; k < 4; k++) {
                    float2 pa = unpack2(accB[k]);
                    float cn0 = cv[2 * k] * bna[o0 + 2 * k] + bnb[o0 + 2 * k];
                    float cn1 = cv[2 * k + 1] * bna[o0 + 2 * k + 1] + bnb[o0 + 2 * k + 1];
                    yvB[2 * k] = gelu_f(cn0) + pa.x;
                    yvB[2 * k + 1] = gelu_f(cn1) + pa.y;
                }
            }
        }
        // LayerNorm across the 4 threads of each token (uniform shfl execution)
        float lsA = 0.f, lqA = 0.f, lsB = 0.f, lqB = 0.f;
#pragma unroll
        for (int j = 0; j < 8; j++) {
            lsA += yvA[j]; lqA += yvA[j] * yvA[j];
            lsB += yvB[j]; lqB += yvB[j] * yvB[j];
        }
        lsA += __shfl_xor_sync(0xffffffffu, lsA, 1); lsA += __shfl_xor_sync(0xffffffffu, lsA, 2);
        lqA += __shfl_xor_sync(0xffffffffu, lqA, 1); lqA += __shfl_xor_sync(0xffffffffu, lqA, 2);
        lsB += __shfl_xor_sync(0xffffffffu, lsB, 1); lsB += __shfl_xor_sync(0xffffffffu, lsB, 2);
        lqB += __shfl_xor_sync(0xffffffffu, lqB, 1); lqB += __shfl_xor_sync(0xffffffffu, lqB, 2);
        float mA = lsA * (1.f / 32.f);
        float vA = lqA * (1.f / 32.f) - mA * mA;
        float rA = rsqrtf(vA + 1e-5f);
        float mB = lsB * (1.f / 32.f);
        float vB = lqB * (1.f / 32.f) - mB * mB;
        float rB = rsqrtf(vB + 1e-5f);
        if (vp) {
            float4* yoA = (float4*)&y[sA * 36 + o0];
            if (fvA) {
                float ov[8];
#pragma unroll
                for (int j = 0; j < 8; j++)
                    ov[j] = (yvA[j] - mA) * rA * lg[o0 + j] + lb[o0 + j];
                yoA[0] = make_float4(ov[0], ov[1], ov[2], ov[3]);
                yoA[1] = make_float4(ov[4], ov[5], ov[6], ov[7]);
                if (sA >= 1 && sA <= E) {
                    float4* ho = (float4*)&hdst[(rowbase + fA_) * 32 + o0];
                    ho[0] = make_float4(ov[0], ov[1], ov[2], ov[3]);
                    ho[1] = make_float4(ov[4], ov[5], ov[6], ov[7]);
                }
            } else {
                yoA[0] = make_float4(0.f, 0.f, 0.f, 0.f);
                yoA[1] = make_float4(0.f, 0.f, 0.f, 0.f);
            }
            if (sB < 67) {
                float4* yoB = (float4*)&y[sB * 36 + o0];
                if (fvB) {
                    float ov[8];
#pragma unroll
                    for (int j = 0; j < 8; j++)
                        ov[j] = (yvB[j] - mB) * rB * lg[o0 + j] + lb[o0 + j];
                    yoB[0] = make_float4(ov[0], ov[1], ov[2], ov[3]);
                    yoB[1] = make_float4(ov[4], ov[5], ov[6], ov[7]);
                    if (sB >= 1 && sB <= E) {
                        float4* ho = (float4*)&hdst[(rowbase + fB_) * 32 + o0];
                        ho[0] = make_float4(ov[0], ov[1], ov[2], ov[3]);
                        ho[1] = make_float4(ov[4], ov[5], ov[6], ov[7]);
                    }
                } else {
                    yoB[0] = make_float4(0.f, 0.f, 0.f, 0.f);
                    yoB[1] = make_float4(0.f, 0.f, 0.f, 0.f);
                }
            }
        }
    }
    if (last) return;
    __syncthreads();

    // ---- fused next-layer conv on smem y (zero-padded rows; no tap masks) ----
    conv_phase(y, cw, fb, E, rowbase, (int)blockIdx.y * NBX + blockIdx.x, R1, gc_out);
}

// ===== head: gelu(h@W1+b1) @ W2 + b2 -> sigmoid =====
__global__ __launch_bounds__(256) void k_head(const float* __restrict__ w1,
                                              const float* __restrict__ b1,
                                              const float* __restrict__ w2,
                                              const float* __restrict__ b2,
                                              float* __restrict__ out) {
    __shared__ __align__(16) float hsm[256][33];
    __shared__ __align__(16) float ws1[512];
    __shared__ __align__(16) float wb1[16];
    __shared__ __align__(16) float ws2[16];
    __shared__ float b2s;
    int t0 = blockIdx.x * 256;
    const float* hsrc = g_h[0];
    for (int idx = threadIdx.x; idx < 256 * 32; idx += 256) {
        int tok = idx >> 5, c = idx & 31;
        hsm[tok][c] = hsrc[(size_t)(t0 + tok) * 32 + c];
    }
    for (int idx = threadIdx.x; idx < 512; idx += 256) ws1[idx] = w1[idx];
    if (threadIdx.x < 16) { wb1[threadIdx.x] = b1[threadIdx.x]; ws2[threadIdx.x] = w2[threadIdx.x]; }
    if (threadIdx.x == 0) b2s = b2[0];
    __syncthreads();

    const float* hr = hsm[threadIdx.x];
    u64 s2[8];
    const u64* wb2 = (const u64*)wb1;
#pragma unroll
    for (int k = 0; k < 8; k++) s2[k] = wb2[k];
#pragma unroll
    for (int i = 0; i < 32; i++) {
        u64 a2 = pack2(hr[i]);
        const u64* wr = (const u64*)(ws1 + i * 16);
#pragma unroll
        for (int k = 0; k < 8; k++) ffma2(s2[k], a2, wr[k]);
    }
    float m = b2s;
#pragma unroll
    for (int k = 0; k < 8; k++) {
        float2 f2 = unpack2(s2[k]);
        m += gelu_f(f2.x) * ws2[2 * k] + gelu_f(f2.y) * ws2[2 * k + 1];
    }
    out[t0 + threadIdx.x] = 1.f / (1.f + expf(-m));
}

// ===== launcher =====
extern "C" void kernel_launch(void* const* d_in, const int* in_sizes, int n_in,
                              void* d_out, int out_size) {
    const float* x      = (const float*)d_in[0];
    const float* in_w   = (const float*)d_in[1];
    const float* in_b   = (const float*)d_in[2];
    const float* conv_w = (const float*)d_in[3];
    const float* bn_g   = (const float*)d_in[4];
    const float* bn_b   = (const float*)d_in[5];
    const float* qkv_w  = (const float*)d_in[6];
    const float* proj_w = (const float*)d_in[7];
    const float* proj_b = (const float*)d_in[8];
    const float* ln_g   = (const float*)d_in[9];
    const float* ln_b   = (const float*)d_in[10];
    const float* h1_w   = (const float*)d_in[11];
    const float* h1_b   = (const float*)d_in[12];
    const float* h2_w   = (const float*)d_in[13];
    const float* h2_b   = (const float*)d_in[14];
    float* out = (float*)d_out;

    cudaFuncSetAttribute(k_apply, cudaFuncAttributeMaxDynamicSharedMemorySize, SMEM_APPLY);

    dim3 grid(NBX, B_N);
    k_pre<<<grid, NTH>>>(x, in_w, in_b, conv_w);
    for (int l = 0; l < 4; l++) {
        int src = l & 1;
        int cidx = l & 1;   // layer l reads g_c[l&1], writes g_c[(l&1)^1]
        int last = (l == 3) ? 1 : 0;
        k_bnfin<<<32, 256>>>(bn_g + l * 32, bn_b + l * 32);
        k_apply<<<grid, NTH, SMEM_APPLY>>>(qkv_w + l * 3072, proj_w + l * 1024,
                                           proj_b + l * 32, ln_g + l * 32, ln_b + l * 32,
                                           conv_w + (l + 1 < 4 ? l + 1 : 0) * 3072,
                                           src, cidx, last);
    }
    k_head<<<BF_N / 256, 256>>>(h1_w, h1_b, h2_w, h2_b, out);
}